// round 2
// baseline (speedup 1.0000x reference)
#include <cuda_runtime.h>
#include <cuda_bf16.h>
#include <math.h>

// ---------------- constants ----------------
#define T_TOK   1024     // B*S
#define D_MODEL 256
#define SEQ     512
#define NHEAD   4
#define DHEAD   64
#define NBASIS  32
#define RRANK   64
#define NNEUR   64
#define TOPK    8
#define DFF     1024
#define NLAYER  4
#define VOCAB   32000

// ---------------- scratch (device globals; no allocs allowed) ----------------
__device__ float g_x[T_TOK * D_MODEL];
__device__ float g_nrm1[T_TOK * D_MODEL];
__device__ float g_q[T_TOK * D_MODEL];
__device__ float g_k[T_TOK * D_MODEL];
__device__ float g_v[T_TOK * D_MODEL];
__device__ float g_ctx[T_TOK * D_MODEL];
__device__ float g_query[T_TOK * D_MODEL];
__device__ float g_nrm2[T_TOK * D_MODEL];
__device__ float g_scores[T_TOK * NNEUR];
__device__ float g_wr[T_TOK * NBASIS];
__device__ float g_h[T_TOK * 64];
__device__ float g_ffn[T_TOK * DFF];
__device__ float g_Rsoft[NNEUR * NBASIS];
__device__ float g_nemb[NNEUR * D_MODEL];

// ---------------- embed ----------------
__global__ void embed_kernel(const int* __restrict__ ids, const float* __restrict__ te,
                             const float* __restrict__ pe, float* __restrict__ x) {
    int t = blockIdx.x, d = threadIdx.x;
    int s = t & (SEQ - 1);
    x[t * 256 + d] = te[ids[t] * 256 + d] + pe[s * 256 + d];
}

// ---------------- layernorm ----------------
__global__ void ln_kernel(const float* __restrict__ x, const float* __restrict__ g,
                          const float* __restrict__ b, float* __restrict__ out) {
    int t = blockIdx.x, d = threadIdx.x;  // 256 threads
    __shared__ float red[256];
    float v = x[t * 256 + d];
    red[d] = v;
    __syncthreads();
    for (int s = 128; s > 0; s >>= 1) { if (d < s) red[d] += red[d + s]; __syncthreads(); }
    float mean = red[0] * (1.f / 256.f);
    __syncthreads();
    float c = v - mean;
    red[d] = c * c;
    __syncthreads();
    for (int s = 128; s > 0; s >>= 1) { if (d < s) red[d] += red[d + s]; __syncthreads(); }
    float var = red[0] * (1.f / 256.f);
    out[t * 256 + d] = c * rsqrtf(var + 1e-5f) * g[d] + b[d];
}

// ---------------- GEMM: C[M,N] = A[M,K] @ B (+bias) (+beta*C) ----------------
// BT=0: B is [K,N] row-major. BT=1: B is [N,K] row-major (C = A @ B^T).
// Requires M%64==0, N%64==0, K%16==0 (all our shapes satisfy this).
template <int BT>
__global__ void gemm64_kernel(const float* __restrict__ A, const float* __restrict__ B,
                              const float* __restrict__ bias, float* __restrict__ C,
                              int M, int N, int K, float beta) {
    __shared__ __align__(16) float As[16 * 68];
    __shared__ __align__(16) float Bs[16 * 68];
    int tid = threadIdx.x;
    int tx = tid & 15, ty = tid >> 4;
    int m0 = blockIdx.y * 64, n0 = blockIdx.x * 64;
    float acc[4][4];
#pragma unroll
    for (int i = 0; i < 4; i++)
#pragma unroll
        for (int j = 0; j < 4; j++) acc[i][j] = 0.f;

    for (int k0 = 0; k0 < K; k0 += 16) {
#pragma unroll
        for (int it = 0; it < 4; it++) {
            int idx = tid + it * 256;
            int ka = idx & 15, ma = idx >> 4;
            As[ka * 68 + ma] = A[(m0 + ma) * K + k0 + ka];
            if (BT) {
                Bs[ka * 68 + ma] = B[(n0 + ma) * K + k0 + ka];
            } else {
                int nb = idx & 63, kb = idx >> 6;
                Bs[kb * 68 + nb] = B[(k0 + kb) * N + n0 + nb];
            }
        }
        __syncthreads();
#pragma unroll
        for (int kk = 0; kk < 16; kk++) {
            float4 av = *(const float4*)&As[kk * 68 + ty * 4];
            float4 bv = *(const float4*)&Bs[kk * 68 + tx * 4];
            float a[4] = {av.x, av.y, av.z, av.w};
            float bb[4] = {bv.x, bv.y, bv.z, bv.w};
#pragma unroll
            for (int i = 0; i < 4; i++)
#pragma unroll
                for (int j = 0; j < 4; j++) acc[i][j] = fmaf(a[i], bb[j], acc[i][j]);
        }
        __syncthreads();
    }
#pragma unroll
    for (int i = 0; i < 4; i++) {
        int m = m0 + ty * 4 + i;
#pragma unroll
        for (int j = 0; j < 4; j++) {
            int n = n0 + tx * 4 + j;
            float val = acc[i][j];
            if (bias) val += bias[n];
            if (beta != 0.f) val += C[m * N + n];
            C[m * N + n] = val;
        }
    }
}

// ---------------- attention: one block per (b,h,query) ----------------
__global__ void attn_kernel(const float* __restrict__ q, const float* __restrict__ k,
                            const float* __restrict__ v, float* __restrict__ ctx) {
    int bid = blockIdx.x;
    int qi = bid & (SEQ - 1);
    int h  = (bid >> 9) & (NHEAD - 1);
    int b  = bid >> 11;
    int t  = b * SEQ + qi;
    int tid = threadIdx.x, warp = tid >> 5, lane = tid & 31;
    __shared__ float sc[SEQ];
    __shared__ float qs[DHEAD];
    __shared__ float red[4];
    __shared__ float cbuf[DHEAD];

    if (tid < DHEAD) qs[tid] = q[t * 256 + h * 64 + tid];
    __syncthreads();
    int nk = qi + 1;
    for (int j = warp; j < nk; j += 4) {
        const float* kr = k + (b * SEQ + j) * 256 + h * 64;
        float p = qs[lane] * kr[lane] + qs[lane + 32] * kr[lane + 32];
#pragma unroll
        for (int o = 16; o; o >>= 1) p += __shfl_down_sync(0xffffffffu, p, o);
        if (!lane) sc[j] = p * 0.125f;  // 1/sqrt(64)
    }
    __syncthreads();
    float m = -1e30f;
    for (int j = tid; j < nk; j += 128) m = fmaxf(m, sc[j]);
#pragma unroll
    for (int o = 16; o; o >>= 1) m = fmaxf(m, __shfl_xor_sync(0xffffffffu, m, o));
    if (!lane) red[warp] = m;
    __syncthreads();
    m = fmaxf(fmaxf(red[0], red[1]), fmaxf(red[2], red[3]));
    __syncthreads();
    float ssum = 0.f;
    for (int j = tid; j < nk; j += 128) { float e = expf(sc[j] - m); sc[j] = e; ssum += e; }
#pragma unroll
    for (int o = 16; o; o >>= 1) ssum += __shfl_xor_sync(0xffffffffu, ssum, o);
    if (!lane) red[warp] = ssum;
    __syncthreads();
    float inv = 1.f / (red[0] + red[1] + red[2] + red[3]);
    int d = tid & 63, half = tid >> 6;
    float acc = 0.f;
    for (int j = half; j < nk; j += 2) acc += sc[j] * v[(b * SEQ + j) * 256 + h * 64 + d];
    if (!half) cbuf[d] = acc;
    __syncthreads();
    if (half) ctx[t * 256 + h * 64 + d] = (cbuf[d] + acc) * inv;
}

// ---------------- per-layer recipe softmax + neuron embeddings ----------------
__global__ void rsoft_kernel(const float* __restrict__ recipes, const float* __restrict__ basis,
                             float* __restrict__ Rsoft, float* __restrict__ nemb) {
    int tid = threadIdx.x;  // 256
    __shared__ float rs[NNEUR * NBASIS];
    if (tid < NNEUR) {
        float row[NBASIS];
        float mx = -1e30f;
        for (int nb = 0; nb < NBASIS; nb++) { row[nb] = recipes[tid * NBASIS + nb]; mx = fmaxf(mx, row[nb]); }
        float s = 0.f;
        for (int nb = 0; nb < NBASIS; nb++) { row[nb] = expf(row[nb] - mx); s += row[nb]; }
        float invs = 1.f / s;
        for (int nb = 0; nb < NBASIS; nb++) {
            float vv = row[nb] * invs;
            rs[tid * NBASIS + nb] = vv;
            Rsoft[tid * NBASIS + nb] = vv;
        }
    }
    __syncthreads();
    for (int i = tid; i < NNEUR * D_MODEL; i += 256) {
        int n = i >> 8, d = i & 255;
        float s = 0.f;
        for (int nb = 0; nb < NBASIS; nb++) s = fmaf(rs[n * NBASIS + nb], basis[nb * 256 + d], s);
        nemb[i] = s;
    }
}

// ---------------- router: topk(8) + softmax + wr ----------------
__global__ void router_kernel(const float* __restrict__ scores, const float* __restrict__ Rsoft,
                              float* __restrict__ wr) {
    int t = blockIdx.x;
    int tid = threadIdx.x;  // 32
    __shared__ float sc[NNEUR];
    __shared__ int   idx[TOPK];
    __shared__ float w[TOPK];
    sc[tid] = scores[t * NNEUR + tid];
    sc[tid + 32] = scores[t * NNEUR + 32 + tid];
    __syncthreads();
    if (tid == 0) {
        float vals[TOPK];
        for (int kk = 0; kk < TOPK; kk++) {
            float best = -1e30f; int bi = 0;
            for (int n = 0; n < NNEUR; n++) if (sc[n] > best) { best = sc[n]; bi = n; }
            vals[kk] = best; idx[kk] = bi; sc[bi] = -1e30f;
        }
        float mx = vals[0];
        float e[TOPK], s = 0.f;
        for (int kk = 0; kk < TOPK; kk++) { e[kk] = expf(vals[kk] - mx); s += e[kk]; }
        float invs = 1.f / s;
        for (int kk = 0; kk < TOPK; kk++) w[kk] = e[kk] * invs;
    }
    __syncthreads();
    float acc = 0.f;
#pragma unroll
    for (int kk = 0; kk < TOPK; kk++) acc = fmaf(w[kk], Rsoft[idx[kk] * NBASIS + tid], acc);
    wr[t * NBASIS + tid] = acc;
}

// ---------------- TT FFN stage A: nrm2 [16x16] -> h [8x8], rank-slice streamed ----------------
// 8 tokens per block, 256 threads (one warp per token).
struct SmemA {
    float A1s[4096];        // slice r: [n][i][k] 32x16x8
    float A2s[4096];        // slice r: [n][j][l] 32x16x8
    float xf[8][256];
    float wrs[8][32];
    float a1[8][128];
    float a2[8][128];
    float tr[8][128];
};

__global__ void stageA_kernel(const float* __restrict__ nrm2, const float* __restrict__ wr,
                              const float* __restrict__ A1g, const float* __restrict__ A2g,
                              float* __restrict__ hout) {
    extern __shared__ float smemraw[];
    SmemA& S = *reinterpret_cast<SmemA*>(smemraw);
    int tid = threadIdx.x, tg = tid >> 5, lane = tid & 31;
    int t0 = blockIdx.x * 8;
    for (int i = tid; i < 8 * 256; i += 256) S.xf[0][i] = nrm2[t0 * 256 + i];
    for (int i = tid; i < 8 * 32; i += 256)  S.wrs[0][i] = wr[t0 * 32 + i];
    __syncthreads();
    float wreg[32];
#pragma unroll
    for (int n = 0; n < 32; n++) wreg[n] = S.wrs[tg][n];
    float hacc0 = 0.f, hacc1 = 0.f;
    int o = lane * 4;

    for (int r = 0; r < RRANK; r++) {
        __syncthreads();
        for (int i = tid; i < 4096; i += 256) {
            int n = i >> 7, rest = i & 127;
            S.A1s[i] = A1g[(n * 16 + (rest >> 3)) * 512 + r * 8 + (rest & 7)];
            S.A2s[i] = A2g[(n * 64 + r) * 128 + rest];
        }
        __syncthreads();
        // mix slices for this token
        float m0 = 0, m1 = 0, m2 = 0, m3 = 0, p0 = 0, p1 = 0, p2 = 0, p3 = 0;
#pragma unroll
        for (int n = 0; n < 32; n++) {
            float ww = wreg[n];
            const float* s1 = &S.A1s[n * 128 + o];
            const float* s2 = &S.A2s[n * 128 + o];
            m0 = fmaf(ww, s1[0], m0); m1 = fmaf(ww, s1[1], m1);
            m2 = fmaf(ww, s1[2], m2); m3 = fmaf(ww, s1[3], m3);
            p0 = fmaf(ww, s2[0], p0); p1 = fmaf(ww, s2[1], p1);
            p2 = fmaf(ww, s2[2], p2); p3 = fmaf(ww, s2[3], p3);
        }
        S.a1[tg][o] = m0; S.a1[tg][o + 1] = m1; S.a1[tg][o + 2] = m2; S.a1[tg][o + 3] = m3;
        S.a2[tg][o] = p0; S.a2[tg][o + 1] = p1; S.a2[tg][o + 2] = p2; S.a2[tg][o + 3] = p3;
        __syncwarp();
        // t_r[j,k] = sum_i xf[i,j] * a1[i,k]
#pragma unroll
        for (int qd = 0; qd < 4; qd++) {
            int idx = o + qd; int j = idx >> 3, kk = idx & 7;
            float s = 0.f;
#pragma unroll
            for (int i2 = 0; i2 < 16; i2++) s = fmaf(S.xf[tg][i2 * 16 + j], S.a1[tg][i2 * 8 + kk], s);
            S.tr[tg][idx] = s;
        }
        __syncwarp();
        // h[k,l] += sum_j t_r[j,k] * a2[j,l]
#pragma unroll
        for (int qd = 0; qd < 2; qd++) {
            int idx = lane * 2 + qd; int kk = idx >> 3, l = idx & 7;
            float s = 0.f;
#pragma unroll
            for (int j = 0; j < 16; j++) s = fmaf(S.tr[tg][j * 8 + kk], S.a2[tg][j * 8 + l], s);
            if (qd == 0) hacc0 += s; else hacc1 += s;
        }
    }
    hout[(t0 + tg) * 64 + lane * 2]     = hacc0;
    hout[(t0 + tg) * 64 + lane * 2 + 1] = hacc1;
}

// ---------------- TT FFN stage B: h [8x8] -> gelu(out) [32x32], rank-slice streamed ----------------
struct SmemB {
    float B1s[8192];        // slice r: [n][i][k] 32x8x32
    float B2s[8192];        // slice r: [n][j][l] 32x8x32
    float hf[8][64];
    float wrs[8][32];
    float b1[8][256];
    float b2[8][256];
    float tr[8][256];
};

__global__ void stageB_kernel(const float* __restrict__ hin, const float* __restrict__ wr,
                              const float* __restrict__ B1g, const float* __restrict__ B2g,
                              float* __restrict__ ffn) {
    extern __shared__ float smemraw[];
    SmemB& S = *reinterpret_cast<SmemB*>(smemraw);
    int tid = threadIdx.x, tg = tid >> 5, lane = tid & 31;
    int t0 = blockIdx.x * 8;
    for (int i = tid; i < 8 * 64; i += 256) S.hf[0][i]  = hin[t0 * 64 + i];
    for (int i = tid; i < 8 * 32; i += 256) S.wrs[0][i] = wr[t0 * 32 + i];
    __syncthreads();
    float wreg[32];
#pragma unroll
    for (int n = 0; n < 32; n++) wreg[n] = S.wrs[tg][n];
    float oreg[32];
#pragma unroll
    for (int i = 0; i < 32; i++) oreg[i] = 0.f;

    for (int r = 0; r < RRANK; r++) {
        __syncthreads();
        for (int i = tid; i < 8192; i += 256) {
            int n = i >> 8, rest = i & 255;
            S.B1s[i] = B1g[(n * 8 + (rest >> 5)) * 2048 + r * 32 + (rest & 31)];
            S.B2s[i] = B2g[(n * 64 + r) * 256 + rest];
        }
        __syncthreads();
        // mix slices
#pragma unroll
        for (int qd = 0; qd < 8; qd++) {
            int idx = lane + 32 * qd;
            float s1 = 0.f, s2 = 0.f;
#pragma unroll
            for (int n = 0; n < 32; n++) {
                s1 = fmaf(wreg[n], S.B1s[n * 256 + idx], s1);
                s2 = fmaf(wreg[n], S.B2s[n * 256 + idx], s2);
            }
            S.b1[tg][idx] = s1; S.b2[tg][idx] = s2;
        }
        __syncwarp();
        // t_r[j,k] = sum_i hf[i,j] * b1[i,k]   (j = qd, k = lane)
#pragma unroll
        for (int qd = 0; qd < 8; qd++) {
            int idx = lane + 32 * qd;
            float s = 0.f;
#pragma unroll
            for (int i2 = 0; i2 < 8; i2++) s = fmaf(S.hf[tg][i2 * 8 + qd], S.b1[tg][i2 * 32 + lane], s);
            S.tr[tg][idx] = s;
        }
        __syncwarp();
        // out[k,l] += sum_j t_r[j,k] * b2[j,l]  (k = qd, l = lane)
#pragma unroll
        for (int qd = 0; qd < 32; qd++) {
            float s = 0.f;
#pragma unroll
            for (int j = 0; j < 8; j++) s = fmaf(S.tr[tg][j * 32 + qd], S.b2[tg][j * 32 + lane], s);
            oreg[qd] += s;
        }
    }
    int t = t0 + tg;
#pragma unroll
    for (int qd = 0; qd < 32; qd++) {
        float xv = oreg[qd];
        float gv = 0.5f * xv * (1.f + erff(xv * 0.70710678118654752f));
        ffn[t * 1024 + qd * 32 + lane] = gv;
    }
}

// ---------------- host orchestration ----------------
extern "C" void kernel_launch(void* const* d_in, const int* in_sizes, int n_in,
                              void* d_out, int out_size) {
    const int*   ids    = (const int*)d_in[0];
    const float* te     = (const float*)d_in[1];
    const float* pe     = (const float*)d_in[2];
    const float* qW     = (const float*)d_in[3];
    const float* qb     = (const float*)d_in[4];
    const float* kW     = (const float*)d_in[5];
    const float* kb     = (const float*)d_in[6];
    const float* vW     = (const float*)d_in[7];
    const float* vb     = (const float*)d_in[8];
    const float* sW     = (const float*)d_in[9];
    const float* sb     = (const float*)d_in[10];
    const float* recipes= (const float*)d_in[11];
    const float* wdW    = (const float*)d_in[12];
    const float* wdb    = (const float*)d_in[13];
    const float* n1g    = (const float*)d_in[14];
    const float* n1b    = (const float*)d_in[15];
    const float* n2g    = (const float*)d_in[16];
    const float* n2b    = (const float*)d_in[17];
    const float* basis  = (const float*)d_in[18];
    const float* A1     = (const float*)d_in[19];
    const float* A2     = (const float*)d_in[20];
    const float* B1     = (const float*)d_in[21];
    const float* B2     = (const float*)d_in[22];
    const float* fng    = (const float*)d_in[23];
    const float* fnb    = (const float*)d_in[24];
    float* out = (float*)d_out;

    // resolve device-global pointers
    float *x, *nrm1, *q, *k, *v, *ctx, *query, *nrm2, *scores, *wrp, *h, *ffn, *Rsoft, *nemb;
    cudaGetSymbolAddress((void**)&x, g_x);
    cudaGetSymbolAddress((void**)&nrm1, g_nrm1);
    cudaGetSymbolAddress((void**)&q, g_q);
    cudaGetSymbolAddress((void**)&k, g_k);
    cudaGetSymbolAddress((void**)&v, g_v);
    cudaGetSymbolAddress((void**)&ctx, g_ctx);
    cudaGetSymbolAddress((void**)&query, g_query);
    cudaGetSymbolAddress((void**)&nrm2, g_nrm2);
    cudaGetSymbolAddress((void**)&scores, g_scores);
    cudaGetSymbolAddress((void**)&wrp, g_wr);
    cudaGetSymbolAddress((void**)&h, g_h);
    cudaGetSymbolAddress((void**)&ffn, g_ffn);
    cudaGetSymbolAddress((void**)&Rsoft, g_Rsoft);
    cudaGetSymbolAddress((void**)&nemb, g_nemb);

    cudaFuncSetAttribute(stageA_kernel, cudaFuncAttributeMaxDynamicSharedMemorySize, (int)sizeof(SmemA));
    cudaFuncSetAttribute(stageB_kernel, cudaFuncAttributeMaxDynamicSharedMemorySize, (int)sizeof(SmemB));

    embed_kernel<<<T_TOK, 256>>>(ids, te, pe, x);

    dim3 g44(4, 16);   // N=256
    for (int l = 0; l < NLAYER; l++) {
        ln_kernel<<<T_TOK, 256>>>(x, n1g + l * 256, n1b + l * 256, nrm1);
        gemm64_kernel<0><<<g44, 256>>>(nrm1, qW + l * 65536, qb + l * 256, q, 1024, 256, 256, 0.f);
        gemm64_kernel<0><<<g44, 256>>>(nrm1, kW + l * 65536, kb + l * 256, k, 1024, 256, 256, 0.f);
        gemm64_kernel<0><<<g44, 256>>>(nrm1, vW + l * 65536, vb + l * 256, v, 1024, 256, 256, 0.f);
        attn_kernel<<<T_TOK * NHEAD, 128>>>(q, k, v, ctx);
        gemm64_kernel<0><<<g44, 256>>>(nrm1, sW + l * 131072,          nullptr,      query, 1024, 256, 256, 0.f);
        gemm64_kernel<0><<<g44, 256>>>(ctx,  sW + l * 131072 + 65536,  sb + l * 256, query, 1024, 256, 256, 1.f);
        rsoft_kernel<<<1, 256>>>(recipes + l * 2048, basis, Rsoft, nemb);
        gemm64_kernel<1><<<dim3(1, 16), 256>>>(query, nemb, nullptr, scores, 1024, 64, 256, 0.f);
        router_kernel<<<T_TOK, 32>>>(scores, Rsoft, wrp);
        ln_kernel<<<T_TOK, 256>>>(x, n2g + l * 256, n2b + l * 256, nrm2);
        stageA_kernel<<<128, 256, sizeof(SmemA)>>>(nrm2, wrp, A1, A2, h);
        stageB_kernel<<<128, 256, sizeof(SmemB)>>>(h, wrp, B1, B2, ffn);
        gemm64_kernel<0><<<g44, 256>>>(ffn, wdW + l * 262144, wdb + l * 256, x, 1024, 256, 1024, 1.f);
    }
    ln_kernel<<<T_TOK, 256>>>(x, fng, fnb, nrm1);
    gemm64_kernel<1><<<dim3(500, 16), 256>>>(nrm1, te, nullptr, out, 1024, VOCAB, 256, 0.f);
}

// round 3
// speedup vs baseline: 1.3668x; 1.3668x over previous
#include <cuda_runtime.h>
#include <cuda_bf16.h>
#include <math.h>

// ---------------- constants ----------------
#define T_TOK   1024     // B*S
#define D_MODEL 256
#define SEQ     512
#define NHEAD   4
#define DHEAD   64
#define NBASIS  32
#define RRANK   64
#define NNEUR   64
#define TOPK    8
#define DFF     1024
#define NLAYER  4
#define VOCAB   32000
#define RGROUPS 8        // rank split groups
#define RPER    (RRANK / RGROUPS)
#define TPB_FFN 16       // tokens per FFN block

// ---------------- scratch (device globals; no allocs allowed) ----------------
__device__ float g_x[T_TOK * D_MODEL];
__device__ float g_nrm1[T_TOK * D_MODEL];
__device__ float g_q[T_TOK * D_MODEL];
__device__ float g_k[T_TOK * D_MODEL];
__device__ float g_v[T_TOK * D_MODEL];
__device__ float g_ctx[T_TOK * D_MODEL];
__device__ float g_query[T_TOK * D_MODEL];
__device__ float g_nrm2[T_TOK * D_MODEL];
__device__ float g_wr[T_TOK * NBASIS];
__device__ float g_h[T_TOK * 64];
__device__ float g_ffn[T_TOK * DFF];
__device__ float g_Rsoft[NNEUR * NBASIS];
__device__ float g_nemb[NNEUR * D_MODEL];
__device__ float g_hpart[RGROUPS * T_TOK * 64];
__device__ float g_ffnpart[RGROUPS * T_TOK * DFF];

// ---------------- embed ----------------
__global__ void embed_kernel(const int* __restrict__ ids, const float* __restrict__ te,
                             const float* __restrict__ pe, float* __restrict__ x) {
    int t = blockIdx.x, d = threadIdx.x;
    int s = t & (SEQ - 1);
    x[t * 256 + d] = te[ids[t] * 256 + d] + pe[s * 256 + d];
}

// ---------------- layernorm ----------------
__global__ void ln_kernel(const float* __restrict__ x, const float* __restrict__ g,
                          const float* __restrict__ b, float* __restrict__ out) {
    int t = blockIdx.x, d = threadIdx.x;  // 256 threads
    __shared__ float red[256];
    float v = x[t * 256 + d];
    red[d] = v;
    __syncthreads();
    for (int s = 128; s > 0; s >>= 1) { if (d < s) red[d] += red[d + s]; __syncthreads(); }
    float mean = red[0] * (1.f / 256.f);
    __syncthreads();
    float c = v - mean;
    red[d] = c * c;
    __syncthreads();
    for (int s = 128; s > 0; s >>= 1) { if (d < s) red[d] += red[d + s]; __syncthreads(); }
    float var = red[0] * (1.f / 256.f);
    out[t * 256 + d] = c * rsqrtf(var + 1e-5f) * g[d] + b[d];
}

// ---------------- generic 64x64 GEMM: C = A @ B (+bias) (+beta*C) ----------------
template <int BT>
__global__ void gemm64_kernel(const float* __restrict__ A, const float* __restrict__ B,
                              const float* __restrict__ bias, float* __restrict__ C,
                              int M, int N, int K, float beta) {
    __shared__ __align__(16) float As[16 * 68];
    __shared__ __align__(16) float Bs[16 * 68];
    int tid = threadIdx.x;
    int tx = tid & 15, ty = tid >> 4;
    int m0 = blockIdx.y * 64, n0 = blockIdx.x * 64;
    float acc[4][4];
#pragma unroll
    for (int i = 0; i < 4; i++)
#pragma unroll
        for (int j = 0; j < 4; j++) acc[i][j] = 0.f;

    for (int k0 = 0; k0 < K; k0 += 16) {
#pragma unroll
        for (int it = 0; it < 4; it++) {
            int idx = tid + it * 256;
            int ka = idx & 15, ma = idx >> 4;
            As[ka * 68 + ma] = A[(m0 + ma) * K + k0 + ka];
            if (BT) {
                Bs[ka * 68 + ma] = B[(n0 + ma) * K + k0 + ka];
            } else {
                int nb = idx & 63, kb = idx >> 6;
                Bs[kb * 68 + nb] = B[(k0 + kb) * N + n0 + nb];
            }
        }
        __syncthreads();
#pragma unroll
        for (int kk = 0; kk < 16; kk++) {
            float4 av = *(const float4*)&As[kk * 68 + ty * 4];
            float4 bv = *(const float4*)&Bs[kk * 68 + tx * 4];
            float a[4] = {av.x, av.y, av.z, av.w};
            float bb[4] = {bv.x, bv.y, bv.z, bv.w};
#pragma unroll
            for (int i = 0; i < 4; i++)
#pragma unroll
                for (int j = 0; j < 4; j++) acc[i][j] = fmaf(a[i], bb[j], acc[i][j]);
        }
        __syncthreads();
    }
#pragma unroll
    for (int i = 0; i < 4; i++) {
        int m = m0 + ty * 4 + i;
#pragma unroll
        for (int j = 0; j < 4; j++) {
            int n = n0 + tx * 4 + j;
            float val = acc[i][j];
            if (bias) val += bias[n];
            if (beta != 0.f) val += C[m * N + n];
            C[m * N + n] = val;
        }
    }
}

// ---------------- batched 64x64 GEMM: 4 weight matrices, shared A ----------------
struct W4 { const float* W[4]; const float* bias[4]; float* out[4]; };

__global__ void gemm64b_kernel(const float* __restrict__ A, W4 gb, int M, int N, int K) {
    const float* __restrict__ B = gb.W[blockIdx.z];
    const float* __restrict__ bias = gb.bias[blockIdx.z];
    float* __restrict__ C = gb.out[blockIdx.z];
    __shared__ __align__(16) float As[16 * 68];
    __shared__ __align__(16) float Bs[16 * 68];
    int tid = threadIdx.x;
    int tx = tid & 15, ty = tid >> 4;
    int m0 = blockIdx.y * 64, n0 = blockIdx.x * 64;
    float acc[4][4];
#pragma unroll
    for (int i = 0; i < 4; i++)
#pragma unroll
        for (int j = 0; j < 4; j++) acc[i][j] = 0.f;

    for (int k0 = 0; k0 < K; k0 += 16) {
#pragma unroll
        for (int it = 0; it < 4; it++) {
            int idx = tid + it * 256;
            int ka = idx & 15, ma = idx >> 4;
            As[ka * 68 + ma] = A[(m0 + ma) * K + k0 + ka];
            int nb = idx & 63, kb = idx >> 6;
            Bs[kb * 68 + nb] = B[(k0 + kb) * N + n0 + nb];
        }
        __syncthreads();
#pragma unroll
        for (int kk = 0; kk < 16; kk++) {
            float4 av = *(const float4*)&As[kk * 68 + ty * 4];
            float4 bv = *(const float4*)&Bs[kk * 68 + tx * 4];
            float a[4] = {av.x, av.y, av.z, av.w};
            float bb[4] = {bv.x, bv.y, bv.z, bv.w};
#pragma unroll
            for (int i = 0; i < 4; i++)
#pragma unroll
                for (int j = 0; j < 4; j++) acc[i][j] = fmaf(a[i], bb[j], acc[i][j]);
        }
        __syncthreads();
    }
#pragma unroll
    for (int i = 0; i < 4; i++) {
        int m = m0 + ty * 4 + i;
#pragma unroll
        for (int j = 0; j < 4; j++) {
            int n = n0 + tx * 4 + j;
            float val = acc[i][j];
            if (bias) val += bias[n];
            C[m * N + n] = val;
        }
    }
}

// ---------------- head GEMM: C[M,N] = A[M,K] @ B^T, B is [N,K] ----------------
// 128x64 tile, 8x4 micro-tile, 256 threads.
__global__ __launch_bounds__(256) void head_gemm(const float* __restrict__ A,
                                                 const float* __restrict__ B,
                                                 float* __restrict__ C,
                                                 int M, int N, int K) {
    __shared__ __align__(16) float As[16][132];
    __shared__ __align__(16) float Bs[16][68];
    int tid = threadIdx.x;
    int tx = tid & 15, ty = tid >> 4;
    int m0 = blockIdx.y * 128, n0 = blockIdx.x * 64;
    float acc[8][4];
#pragma unroll
    for (int i = 0; i < 8; i++)
#pragma unroll
        for (int j = 0; j < 4; j++) acc[i][j] = 0.f;

    for (int k0 = 0; k0 < K; k0 += 16) {
#pragma unroll
        for (int it = 0; it < 2; it++) {
            int slot = tid + it * 256;
            int row = slot >> 2, kq = (slot & 3) * 4;
            float4 va = *(const float4*)&A[(m0 + row) * K + k0 + kq];
            As[kq][row] = va.x; As[kq + 1][row] = va.y; As[kq + 2][row] = va.z; As[kq + 3][row] = va.w;
        }
        {
            int n = tid >> 2, kq = (tid & 3) * 4;
            float4 vb = *(const float4*)&B[(n0 + n) * K + k0 + kq];
            Bs[kq][n] = vb.x; Bs[kq + 1][n] = vb.y; Bs[kq + 2][n] = vb.z; Bs[kq + 3][n] = vb.w;
        }
        __syncthreads();
#pragma unroll
        for (int kk = 0; kk < 16; kk++) {
            float4 a0 = *(const float4*)&As[kk][ty * 8];
            float4 a1 = *(const float4*)&As[kk][ty * 8 + 4];
            float4 bv = *(const float4*)&Bs[kk][tx * 4];
            float a[8] = {a0.x, a0.y, a0.z, a0.w, a1.x, a1.y, a1.z, a1.w};
            float bb[4] = {bv.x, bv.y, bv.z, bv.w};
#pragma unroll
            for (int i = 0; i < 8; i++)
#pragma unroll
                for (int j = 0; j < 4; j++) acc[i][j] = fmaf(a[i], bb[j], acc[i][j]);
        }
        __syncthreads();
    }
#pragma unroll
    for (int i = 0; i < 8; i++) {
        int m = m0 + ty * 8 + i;
        float4 v = make_float4(acc[i][0], acc[i][1], acc[i][2], acc[i][3]);
        *(float4*)&C[m * N + n0 + tx * 4] = v;
    }
}

// ---------------- attention: one block per (b,h,query) ----------------
__global__ void attn_kernel(const float* __restrict__ q, const float* __restrict__ k,
                            const float* __restrict__ v, float* __restrict__ ctx) {
    int bid = blockIdx.x;
    int qi = bid & (SEQ - 1);
    int h  = (bid >> 9) & (NHEAD - 1);
    int b  = bid >> 11;
    int t  = b * SEQ + qi;
    int tid = threadIdx.x, warp = tid >> 5, lane = tid & 31;
    __shared__ float sc[SEQ];
    __shared__ float qs[DHEAD];
    __shared__ float red[4];
    __shared__ float cbuf[DHEAD];

    if (tid < DHEAD) qs[tid] = q[t * 256 + h * 64 + tid];
    __syncthreads();
    int nk = qi + 1;
    for (int j = warp; j < nk; j += 4) {
        const float* kr = k + (b * SEQ + j) * 256 + h * 64;
        float p = qs[lane] * kr[lane] + qs[lane + 32] * kr[lane + 32];
#pragma unroll
        for (int o = 16; o; o >>= 1) p += __shfl_down_sync(0xffffffffu, p, o);
        if (!lane) sc[j] = p * 0.125f;
    }
    __syncthreads();
    float m = -1e30f;
    for (int j = tid; j < nk; j += 128) m = fmaxf(m, sc[j]);
#pragma unroll
    for (int o = 16; o; o >>= 1) m = fmaxf(m, __shfl_xor_sync(0xffffffffu, m, o));
    if (!lane) red[warp] = m;
    __syncthreads();
    m = fmaxf(fmaxf(red[0], red[1]), fmaxf(red[2], red[3]));
    __syncthreads();
    float ssum = 0.f;
    for (int j = tid; j < nk; j += 128) { float e = expf(sc[j] - m); sc[j] = e; ssum += e; }
#pragma unroll
    for (int o = 16; o; o >>= 1) ssum += __shfl_xor_sync(0xffffffffu, ssum, o);
    if (!lane) red[warp] = ssum;
    __syncthreads();
    float inv = 1.f / (red[0] + red[1] + red[2] + red[3]);
    int d = tid & 63, half = tid >> 6;
    float acc = 0.f;
    for (int j = half; j < nk; j += 2) acc += sc[j] * v[(b * SEQ + j) * 256 + h * 64 + d];
    if (!half) cbuf[d] = acc;
    __syncthreads();
    if (half) ctx[t * 256 + h * 64 + d] = (cbuf[d] + acc) * inv;
}

// ---------------- per-layer recipe softmax + neuron embeddings ----------------
__global__ void rsoft_kernel(const float* __restrict__ recipes, const float* __restrict__ basis,
                             float* __restrict__ Rsoft, float* __restrict__ nemb) {
    int tid = threadIdx.x;  // 256
    __shared__ float rs[NNEUR * NBASIS];
    if (tid < NNEUR) {
        float row[NBASIS];
        float mx = -1e30f;
        for (int nb = 0; nb < NBASIS; nb++) { row[nb] = recipes[tid * NBASIS + nb]; mx = fmaxf(mx, row[nb]); }
        float s = 0.f;
        for (int nb = 0; nb < NBASIS; nb++) { row[nb] = expf(row[nb] - mx); s += row[nb]; }
        float invs = 1.f / s;
        for (int nb = 0; nb < NBASIS; nb++) {
            float vv = row[nb] * invs;
            rs[tid * NBASIS + nb] = vv;
            Rsoft[tid * NBASIS + nb] = vv;
        }
    }
    __syncthreads();
    for (int i = tid; i < NNEUR * D_MODEL; i += 256) {
        int n = i >> 8, d = i & 255;
        float s = 0.f;
        for (int nb = 0; nb < NBASIS; nb++) s = fmaf(rs[n * NBASIS + nb], basis[nb * 256 + d], s);
        nemb[i] = s;
    }
}

// ---------------- fused score + router: one block per token, 256 threads ----------------
__global__ void scorerouter_kernel(const float* __restrict__ query, const float* __restrict__ nemb,
                                   const float* __restrict__ Rsoft, float* __restrict__ wr) {
    int t = blockIdx.x;
    int tid = threadIdx.x, warp = tid >> 5, lane = tid & 31;
    __shared__ float qrow[256];
    __shared__ float sc[NNEUR];
    __shared__ int   idxs[TOPK];
    __shared__ float wv[TOPK];
    qrow[tid] = query[t * 256 + tid];
    __syncthreads();
#pragma unroll
    for (int u = 0; u < 8; u++) {
        int n = warp * 8 + u;
        const float* nr = nemb + n * 256;
        float acc = 0.f;
#pragma unroll
        for (int i = 0; i < 8; i++) acc = fmaf(qrow[lane + 32 * i], nr[lane + 32 * i], acc);
#pragma unroll
        for (int o = 16; o; o >>= 1) acc += __shfl_down_sync(0xffffffffu, acc, o);
        if (!lane) sc[n] = acc;
    }
    __syncthreads();
    if (tid == 0) {
        float vals[TOPK];
        for (int kk = 0; kk < TOPK; kk++) {
            float best = -1e30f; int bi = 0;
            for (int n = 0; n < NNEUR; n++) if (sc[n] > best) { best = sc[n]; bi = n; }
            vals[kk] = best; idxs[kk] = bi; sc[bi] = -1e30f;
        }
        float mx = vals[0];
        float e[TOPK], s = 0.f;
        for (int kk = 0; kk < TOPK; kk++) { e[kk] = expf(vals[kk] - mx); s += e[kk]; }
        float invs = 1.f / s;
        for (int kk = 0; kk < TOPK; kk++) wv[kk] = e[kk] * invs;
    }
    __syncthreads();
    if (tid < 32) {
        float acc = 0.f;
#pragma unroll
        for (int kk = 0; kk < TOPK; kk++) acc = fmaf(wv[kk], Rsoft[idxs[kk] * NBASIS + tid], acc);
        wr[t * NBASIS + tid] = acc;
    }
}

// ---------------- TT FFN stage A (rank-split): 16 tokens/block, 512 threads ----------------
struct SmemA {
    float A1s[4096];         // slice r: [n][i][k] 32x16x8
    float A2s[4096];         // slice r: [n][j][l] 32x16x8
    float xf[TPB_FFN][256];
    float wrs[TPB_FFN][32];
    float a1[TPB_FFN][128];
    float a2[TPB_FFN][128];
    float tr[TPB_FFN][128];
};

__global__ __launch_bounds__(512) void stageA_kernel(
        const float* __restrict__ nrm2, const float* __restrict__ wr,
        const float* __restrict__ A1g, const float* __restrict__ A2g,
        float* __restrict__ hpart) {
    extern __shared__ float smemraw[];
    SmemA& S = *reinterpret_cast<SmemA*>(smemraw);
    int tid = threadIdx.x, tg = tid >> 5, lane = tid & 31;
    int t0 = blockIdx.x * TPB_FFN;
    int r0 = blockIdx.y * RPER;
    for (int i = tid; i < TPB_FFN * 256; i += 512) S.xf[0][i] = nrm2[t0 * 256 + i];
    for (int i = tid; i < TPB_FFN * 32; i += 512)  S.wrs[0][i] = wr[t0 * 32 + i];
    __syncthreads();
    float wreg[32];
#pragma unroll
    for (int n = 0; n < 32; n++) wreg[n] = S.wrs[tg][n];
    float hacc0 = 0.f, hacc1 = 0.f;
    int o = lane * 4;

    for (int ri = 0; ri < RPER; ri++) {
        int r = r0 + ri;
        __syncthreads();
        for (int i = tid; i < 4096; i += 512) {
            int n = i >> 7, rest = i & 127;
            S.A1s[i] = A1g[(n * 16 + (rest >> 3)) * 512 + r * 8 + (rest & 7)];
            S.A2s[i] = A2g[(n * 64 + r) * 128 + rest];
        }
        __syncthreads();
        float m0 = 0, m1 = 0, m2 = 0, m3 = 0, p0 = 0, p1 = 0, p2 = 0, p3 = 0;
#pragma unroll
        for (int n = 0; n < 32; n++) {
            float ww = wreg[n];
            const float* s1 = &S.A1s[n * 128 + o];
            const float* s2 = &S.A2s[n * 128 + o];
            m0 = fmaf(ww, s1[0], m0); m1 = fmaf(ww, s1[1], m1);
            m2 = fmaf(ww, s1[2], m2); m3 = fmaf(ww, s1[3], m3);
            p0 = fmaf(ww, s2[0], p0); p1 = fmaf(ww, s2[1], p1);
            p2 = fmaf(ww, s2[2], p2); p3 = fmaf(ww, s2[3], p3);
        }
        S.a1[tg][o] = m0; S.a1[tg][o + 1] = m1; S.a1[tg][o + 2] = m2; S.a1[tg][o + 3] = m3;
        S.a2[tg][o] = p0; S.a2[tg][o + 1] = p1; S.a2[tg][o + 2] = p2; S.a2[tg][o + 3] = p3;
        __syncwarp();
        // t[j,k] = sum_i xf[i,j]*a1[i,k]
#pragma unroll
        for (int qd = 0; qd < 4; qd++) {
            int idx = o + qd; int j = idx >> 3, kk = idx & 7;
            float s = 0.f;
#pragma unroll
            for (int i2 = 0; i2 < 16; i2++) s = fmaf(S.xf[tg][i2 * 16 + j], S.a1[tg][i2 * 8 + kk], s);
            S.tr[tg][idx] = s;
        }
        __syncwarp();
        // h[k,l] += sum_j t[j,k]*a2[j,l]
#pragma unroll
        for (int qd = 0; qd < 2; qd++) {
            int idx = lane * 2 + qd; int kk = idx >> 3, l = idx & 7;
            float s = 0.f;
#pragma unroll
            for (int j = 0; j < 16; j++) s = fmaf(S.tr[tg][j * 8 + kk], S.a2[tg][j * 8 + l], s);
            if (qd == 0) hacc0 += s; else hacc1 += s;
        }
    }
    int t = t0 + tg;
    hpart[(blockIdx.y * T_TOK + t) * 64 + lane * 2]     = hacc0;
    hpart[(blockIdx.y * T_TOK + t) * 64 + lane * 2 + 1] = hacc1;
}

__global__ void hreduce_kernel(const float* __restrict__ hpart, float* __restrict__ h) {
    int idx = blockIdx.x * 256 + threadIdx.x;  // 65536 total
    float s = 0.f;
#pragma unroll
    for (int g = 0; g < RGROUPS; g++) s += hpart[g * (T_TOK * 64) + idx];
    h[idx] = s;
}

// ---------------- TT FFN stage B (rank-split): 16 tokens/block, 512 threads ----------------
struct SmemB {
    float B1s[8192];         // slice r: [n][i][k] 32x8x32
    float B2s[8192];         // slice r: [n][j][l] 32x8x32
    float tr[TPB_FFN][256];
    float hf[TPB_FFN][64];
    float wrs[TPB_FFN][32];
};

__global__ __launch_bounds__(512) void stageB_kernel(
        const float* __restrict__ hin, const float* __restrict__ wr,
        const float* __restrict__ B1g, const float* __restrict__ B2g,
        float* __restrict__ ffnpart) {
    extern __shared__ float smemraw[];
    SmemB& S = *reinterpret_cast<SmemB*>(smemraw);
    int tid = threadIdx.x, tg = tid >> 5, lane = tid & 31;
    int t0 = blockIdx.x * TPB_FFN;
    int r0 = blockIdx.y * RPER;
    for (int i = tid; i < TPB_FFN * 64; i += 512) S.hf[0][i]  = hin[t0 * 64 + i];
    for (int i = tid; i < TPB_FFN * 32; i += 512) S.wrs[0][i] = wr[t0 * 32 + i];
    __syncthreads();
    float wreg[32];
#pragma unroll
    for (int n = 0; n < 32; n++) wreg[n] = S.wrs[tg][n];
    float oreg[32];
#pragma unroll
    for (int i = 0; i < 32; i++) oreg[i] = 0.f;

    for (int ri = 0; ri < RPER; ri++) {
        int r = r0 + ri;
        __syncthreads();
        for (int i = tid; i < 8192; i += 512) {
            int n = i >> 8, rest = i & 255;
            S.B1s[i] = B1g[(n * 8 + (rest >> 5)) * 2048 + r * 32 + (rest & 31)];
            S.B2s[i] = B2g[(n * 64 + r) * 256 + rest];
        }
        __syncthreads();
        // mix slices; keep this lane's column in registers: b1r[i]=b1[i][lane], b2r[j]=b2[j][lane]
        float b1r[8], b2r[8];
#pragma unroll
        for (int qd = 0; qd < 8; qd++) {
            int idx = lane + 32 * qd;
            float s1 = 0.f, s2 = 0.f;
#pragma unroll
            for (int n = 0; n < 32; n++) {
                s1 = fmaf(wreg[n], S.B1s[n * 256 + idx], s1);
                s2 = fmaf(wreg[n], S.B2s[n * 256 + idx], s2);
            }
            b1r[qd] = s1; b2r[qd] = s2;
        }
        // t[j,k=lane] = sum_i hf[i,j]*b1[i,lane]
#pragma unroll
        for (int j = 0; j < 8; j++) {
            float s = 0.f;
#pragma unroll
            for (int i2 = 0; i2 < 8; i2++) s = fmaf(S.hf[tg][i2 * 8 + j], b1r[i2], s);
            S.tr[tg][j * 32 + lane] = s;
        }
        __syncwarp();
        // out[k,l=lane] += sum_j t[j,k]*b2[j,lane]
#pragma unroll
        for (int kk = 0; kk < 32; kk++) {
            float s = 0.f;
#pragma unroll
            for (int j = 0; j < 8; j++) s = fmaf(S.tr[tg][j * 32 + kk], b2r[j], s);
            oreg[kk] += s;
        }
        __syncwarp();
    }
    int t = t0 + tg;
    float* dst = ffnpart + (blockIdx.y * T_TOK + t) * (size_t)DFF;
#pragma unroll
    for (int kk = 0; kk < 32; kk++) dst[kk * 32 + lane] = oreg[kk];
}

__global__ void gelu_reduce_kernel(const float* __restrict__ ffnpart, float* __restrict__ ffn) {
    int idx = blockIdx.x * 256 + threadIdx.x;  // 1048576 total
    float s = 0.f;
#pragma unroll
    for (int g = 0; g < RGROUPS; g++) s += ffnpart[g * (size_t)(T_TOK * DFF) + idx];
    ffn[idx] = 0.5f * s * (1.f + erff(s * 0.70710678118654752f));
}

// ---------------- host orchestration ----------------
extern "C" void kernel_launch(void* const* d_in, const int* in_sizes, int n_in,
                              void* d_out, int out_size) {
    const int*   ids    = (const int*)d_in[0];
    const float* te     = (const float*)d_in[1];
    const float* pe     = (const float*)d_in[2];
    const float* qW     = (const float*)d_in[3];
    const float* qb     = (const float*)d_in[4];
    const float* kW     = (const float*)d_in[5];
    const float* kb     = (const float*)d_in[6];
    const float* vW     = (const float*)d_in[7];
    const float* vb     = (const float*)d_in[8];
    const float* sW     = (const float*)d_in[9];
    const float* sb     = (const float*)d_in[10];
    const float* recipes= (const float*)d_in[11];
    const float* wdW    = (const float*)d_in[12];
    const float* wdb    = (const float*)d_in[13];
    const float* n1g    = (const float*)d_in[14];
    const float* n1b    = (const float*)d_in[15];
    const float* n2g    = (const float*)d_in[16];
    const float* n2b    = (const float*)d_in[17];
    const float* basis  = (const float*)d_in[18];
    const float* A1     = (const float*)d_in[19];
    const float* A2     = (const float*)d_in[20];
    const float* B1     = (const float*)d_in[21];
    const float* B2     = (const float*)d_in[22];
    const float* fng    = (const float*)d_in[23];
    const float* fnb    = (const float*)d_in[24];
    float* out = (float*)d_out;

    float *x, *nrm1, *q, *k, *v, *ctx, *query, *nrm2, *wrp, *h, *ffn, *Rsoft, *nemb, *hpart, *ffnpart;
    cudaGetSymbolAddress((void**)&x, g_x);
    cudaGetSymbolAddress((void**)&nrm1, g_nrm1);
    cudaGetSymbolAddress((void**)&q, g_q);
    cudaGetSymbolAddress((void**)&k, g_k);
    cudaGetSymbolAddress((void**)&v, g_v);
    cudaGetSymbolAddress((void**)&ctx, g_ctx);
    cudaGetSymbolAddress((void**)&query, g_query);
    cudaGetSymbolAddress((void**)&nrm2, g_nrm2);
    cudaGetSymbolAddress((void**)&wrp, g_wr);
    cudaGetSymbolAddress((void**)&h, g_h);
    cudaGetSymbolAddress((void**)&ffn, g_ffn);
    cudaGetSymbolAddress((void**)&Rsoft, g_Rsoft);
    cudaGetSymbolAddress((void**)&nemb, g_nemb);
    cudaGetSymbolAddress((void**)&hpart, g_hpart);
    cudaGetSymbolAddress((void**)&ffnpart, g_ffnpart);

    cudaFuncSetAttribute(stageA_kernel, cudaFuncAttributeMaxDynamicSharedMemorySize, (int)sizeof(SmemA));
    cudaFuncSetAttribute(stageB_kernel, cudaFuncAttributeMaxDynamicSharedMemorySize, (int)sizeof(SmemB));

    embed_kernel<<<T_TOK, 256>>>(ids, te, pe, x);

    dim3 g44(4, 16);
    for (int l = 0; l < NLAYER; l++) {
        ln_kernel<<<T_TOK, 256>>>(x, n1g + l * 256, n1b + l * 256, nrm1);
        W4 gb;
        gb.W[0] = qW + l * 65536;  gb.bias[0] = qb + l * 256; gb.out[0] = q;
        gb.W[1] = kW + l * 65536;  gb.bias[1] = kb + l * 256; gb.out[1] = k;
        gb.W[2] = vW + l * 65536;  gb.bias[2] = vb + l * 256; gb.out[2] = v;
        gb.W[3] = sW + l * 131072; gb.bias[3] = nullptr;      gb.out[3] = query;
        gemm64b_kernel<<<dim3(4, 16, 4), 256>>>(nrm1, gb, 1024, 256, 256);
        attn_kernel<<<T_TOK * NHEAD, 128>>>(q, k, v, ctx);
        gemm64_kernel<0><<<g44, 256>>>(ctx, sW + l * 131072 + 65536, sb + l * 256, query, 1024, 256, 256, 1.f);
        rsoft_kernel<<<1, 256>>>(recipes + l * 2048, basis, Rsoft, nemb);
        scorerouter_kernel<<<T_TOK, 256>>>(query, nemb, Rsoft, wrp);
        ln_kernel<<<T_TOK, 256>>>(x, n2g + l * 256, n2b + l * 256, nrm2);
        stageA_kernel<<<dim3(T_TOK / TPB_FFN, RGROUPS), 512, sizeof(SmemA)>>>(nrm2, wrp, A1, A2, hpart);
        hreduce_kernel<<<T_TOK * 64 / 256, 256>>>(hpart, h);
        stageB_kernel<<<dim3(T_TOK / TPB_FFN, RGROUPS), 512, sizeof(SmemB)>>>(h, wrp, B1, B2, ffnpart);
        gelu_reduce_kernel<<<T_TOK * DFF / 256, 256>>>(ffnpart, ffn);
        gemm64_kernel<0><<<g44, 256>>>(ffn, wdW + l * 262144, wdb + l * 256, x, 1024, 256, 1024, 1.f);
    }
    ln_kernel<<<T_TOK, 256>>>(x, fng, fnb, nrm1);
    head_gemm<<<dim3(VOCAB / 64, T_TOK / 128), 256>>>(nrm1, te, out, 1024, VOCAB, 256);
}

// round 4
// speedup vs baseline: 1.7715x; 1.2960x over previous
#include <cuda_runtime.h>
#include <cuda_bf16.h>
#include <math.h>
#include <stdint.h>

// ---------------- constants ----------------
#define T_TOK   1024
#define D_MODEL 256
#define SEQ     512
#define NHEAD   4
#define DHEAD   64
#define NBASIS  32
#define RRANK   64
#define NNEUR   64
#define TOPK    8
#define DFF     1024
#define NLAYER  4
#define VOCAB   32000
#define RGROUPS 8
#define RPER    (RRANK / RGROUPS)

// ---------------- scratch ----------------
__device__ float g_x[T_TOK * D_MODEL];
__device__ float g_nrm1[T_TOK * D_MODEL];
__device__ float g_q[T_TOK * D_MODEL];
__device__ float g_k[T_TOK * D_MODEL];
__device__ float g_v[T_TOK * D_MODEL];
__device__ float g_ctx[T_TOK * D_MODEL];
__device__ float g_query[T_TOK * D_MODEL];
__device__ float g_nrm2[T_TOK * D_MODEL];
__device__ float g_h[T_TOK * 64];
__device__ float g_ffn[T_TOK * DFF];
__device__ float g_Rsoft[NNEUR * NBASIS];
__device__ float g_nemb[NNEUR * D_MODEL];
__device__ float g_hpart[RGROUPS * T_TOK * 64];
__device__ float g_ffnpart[RGROUPS * T_TOK * DFF];
__device__ int   g_topi[T_TOK * TOPK];
__device__ float g_topw[T_TOK * TOPK];
// neuron cores (per current layer)
__device__ float g_NA1[NNEUR * 8192];   // [n][i(16)][r(64)][k(8)]
__device__ float g_NA2[NNEUR * 8192];   // [n][r(64)][j(16)][l(8)]
__device__ float g_NB1[NNEUR * 16384];  // [n][i(8)][r(64)][k(32)]
__device__ float g_NB2[NNEUR * 16384];  // [n][r(64)][j(8)][l(32)]

// ---------------- helpers: tf32 mma ----------------
__device__ __forceinline__ uint32_t f2tf32(float f) {
    uint32_t u;
    asm("cvt.rna.tf32.f32 %0, %1;" : "=r"(u) : "f"(f));
    return u;
}

__device__ __forceinline__ void mma_tf32(float& c0, float& c1, float& c2, float& c3,
                                         uint32_t a0, uint32_t a1, uint32_t a2, uint32_t a3,
                                         uint32_t b0, uint32_t b1) {
    asm("mma.sync.aligned.m16n8k8.row.col.f32.tf32.tf32.f32 "
        "{%0,%1,%2,%3},{%4,%5,%6,%7},{%8,%9},{%0,%1,%2,%3};"
        : "+f"(c0), "+f"(c1), "+f"(c2), "+f"(c3)
        : "r"(a0), "r"(a1), "r"(a2), "r"(a3), "r"(b0), "r"(b1));
}

// ---------------- embed ----------------
__global__ void embed_kernel(const int* __restrict__ ids, const float* __restrict__ te,
                             const float* __restrict__ pe, float* __restrict__ x) {
    int t = blockIdx.x, d = threadIdx.x;
    int s = t & (SEQ - 1);
    x[t * 256 + d] = te[ids[t] * 256 + d] + pe[s * 256 + d];
}

// ---------------- layernorm ----------------
__global__ void ln_kernel(const float* __restrict__ x, const float* __restrict__ g,
                          const float* __restrict__ b, float* __restrict__ out) {
    int t = blockIdx.x, d = threadIdx.x;
    __shared__ float red[256];
    float v = x[t * 256 + d];
    red[d] = v;
    __syncthreads();
    for (int s = 128; s > 0; s >>= 1) { if (d < s) red[d] += red[d + s]; __syncthreads(); }
    float mean = red[0] * (1.f / 256.f);
    __syncthreads();
    float c = v - mean;
    red[d] = c * c;
    __syncthreads();
    for (int s = 128; s > 0; s >>= 1) { if (d < s) red[d] += red[d + s]; __syncthreads(); }
    float var = red[0] * (1.f / 256.f);
    out[t * 256 + d] = c * rsqrtf(var + 1e-5f) * g[d] + b[d];
}

// ---------------- tf32 tensor-core GEMM: C[M,N] = A@B (+bias)(+beta*C) ----------------
// BT=0: B [K,N] row-major; BT=1: B [N,K] row-major (C = A@B^T).
// Tile 64x64, BK=32, 256 threads (8 warps: 4 in M x 2 in N).
template <int BT>
__global__ __launch_bounds__(256) void tc_gemm(const float* __restrict__ A,
                                               const float* __restrict__ B,
                                               const float* __restrict__ bias,
                                               float* __restrict__ C,
                                               int M, int N, int K, float beta) {
    __shared__ uint32_t As[32 * 68];
    __shared__ uint32_t Bs[32 * 68];
    int tid = threadIdx.x, lane = tid & 31, wid = tid >> 5;
    int wm = (wid & 3) * 16, wn = (wid >> 2) * 32;
    int m0 = blockIdx.y * 64, n0 = blockIdx.x * 64;
    int gid = lane >> 2, tig = lane & 3;
    float acc[4][4];
#pragma unroll
    for (int j = 0; j < 4; j++)
#pragma unroll
        for (int i = 0; i < 4; i++) acc[j][i] = 0.f;

    for (int k0 = 0; k0 < K; k0 += 32) {
#pragma unroll
        for (int it = 0; it < 2; it++) {
            int u = tid + it * 256;
            int row = u >> 3, kq = (u & 7) * 4;
            float4 v = *(const float4*)&A[(size_t)(m0 + row) * K + k0 + kq];
            As[(kq + 0) * 68 + row] = f2tf32(v.x);
            As[(kq + 1) * 68 + row] = f2tf32(v.y);
            As[(kq + 2) * 68 + row] = f2tf32(v.z);
            As[(kq + 3) * 68 + row] = f2tf32(v.w);
        }
#pragma unroll
        for (int it = 0; it < 2; it++) {
            int u = tid + it * 256;
            if (BT) {
                int row = u >> 3, kq = (u & 7) * 4;
                float4 v = *(const float4*)&B[(size_t)(n0 + row) * K + k0 + kq];
                Bs[(kq + 0) * 68 + row] = f2tf32(v.x);
                Bs[(kq + 1) * 68 + row] = f2tf32(v.y);
                Bs[(kq + 2) * 68 + row] = f2tf32(v.z);
                Bs[(kq + 3) * 68 + row] = f2tf32(v.w);
            } else {
                int kb = u >> 4, nq = (u & 15) * 4;
                float4 v = *(const float4*)&B[(size_t)(k0 + kb) * N + n0 + nq];
                Bs[kb * 68 + nq + 0] = f2tf32(v.x);
                Bs[kb * 68 + nq + 1] = f2tf32(v.y);
                Bs[kb * 68 + nq + 2] = f2tf32(v.z);
                Bs[kb * 68 + nq + 3] = f2tf32(v.w);
            }
        }
        __syncthreads();
#pragma unroll
        for (int s = 0; s < 4; s++) {
            int k = s * 8;
            uint32_t a0 = As[(k + tig) * 68 + wm + gid];
            uint32_t a1 = As[(k + tig) * 68 + wm + gid + 8];
            uint32_t a2 = As[(k + 4 + tig) * 68 + wm + gid];
            uint32_t a3 = As[(k + 4 + tig) * 68 + wm + gid + 8];
#pragma unroll
            for (int j = 0; j < 4; j++) {
                uint32_t b0 = Bs[(k + tig) * 68 + wn + j * 8 + gid];
                uint32_t b1 = Bs[(k + 4 + tig) * 68 + wn + j * 8 + gid];
                mma_tf32(acc[j][0], acc[j][1], acc[j][2], acc[j][3], a0, a1, a2, a3, b0, b1);
            }
        }
        __syncthreads();
    }
#pragma unroll
    for (int j = 0; j < 4; j++) {
        int n = n0 + wn + j * 8 + tig * 2;
        int m = m0 + wm + gid;
        float v0 = acc[j][0], v1 = acc[j][1], v2 = acc[j][2], v3 = acc[j][3];
        if (bias) { float b0 = bias[n], b1 = bias[n + 1]; v0 += b0; v1 += b1; v2 += b0; v3 += b1; }
        size_t o0 = (size_t)m * N + n, o1 = (size_t)(m + 8) * N + n;
        if (beta != 0.f) { v0 += C[o0]; v1 += C[o0 + 1]; v2 += C[o1]; v3 += C[o1 + 1]; }
        C[o0] = v0; C[o0 + 1] = v1; C[o1] = v2; C[o1 + 1] = v3;
    }
}

// ---------------- batched tf32 GEMM (4 weights, shared A, B [K,N]) ----------------
struct W4 { const float* W[4]; const float* bias[4]; float* out[4]; };

__global__ __launch_bounds__(256) void tc_gemmb(const float* __restrict__ A, W4 gb,
                                                int M, int N, int K) {
    const float* __restrict__ B = gb.W[blockIdx.z];
    const float* __restrict__ bias = gb.bias[blockIdx.z];
    float* __restrict__ C = gb.out[blockIdx.z];
    __shared__ uint32_t As[32 * 68];
    __shared__ uint32_t Bs[32 * 68];
    int tid = threadIdx.x, lane = tid & 31, wid = tid >> 5;
    int wm = (wid & 3) * 16, wn = (wid >> 2) * 32;
    int m0 = blockIdx.y * 64, n0 = blockIdx.x * 64;
    int gid = lane >> 2, tig = lane & 3;
    float acc[4][4];
#pragma unroll
    for (int j = 0; j < 4; j++)
#pragma unroll
        for (int i = 0; i < 4; i++) acc[j][i] = 0.f;

    for (int k0 = 0; k0 < K; k0 += 32) {
#pragma unroll
        for (int it = 0; it < 2; it++) {
            int u = tid + it * 256;
            int row = u >> 3, kq = (u & 7) * 4;
            float4 v = *(const float4*)&A[(size_t)(m0 + row) * K + k0 + kq];
            As[(kq + 0) * 68 + row] = f2tf32(v.x);
            As[(kq + 1) * 68 + row] = f2tf32(v.y);
            As[(kq + 2) * 68 + row] = f2tf32(v.z);
            As[(kq + 3) * 68 + row] = f2tf32(v.w);
        }
#pragma unroll
        for (int it = 0; it < 2; it++) {
            int u = tid + it * 256;
            int kb = u >> 4, nq = (u & 15) * 4;
            float4 v = *(const float4*)&B[(size_t)(k0 + kb) * N + n0 + nq];
            Bs[kb * 68 + nq + 0] = f2tf32(v.x);
            Bs[kb * 68 + nq + 1] = f2tf32(v.y);
            Bs[kb * 68 + nq + 2] = f2tf32(v.z);
            Bs[kb * 68 + nq + 3] = f2tf32(v.w);
        }
        __syncthreads();
#pragma unroll
        for (int s = 0; s < 4; s++) {
            int k = s * 8;
            uint32_t a0 = As[(k + tig) * 68 + wm + gid];
            uint32_t a1 = As[(k + tig) * 68 + wm + gid + 8];
            uint32_t a2 = As[(k + 4 + tig) * 68 + wm + gid];
            uint32_t a3 = As[(k + 4 + tig) * 68 + wm + gid + 8];
#pragma unroll
            for (int j = 0; j < 4; j++) {
                uint32_t b0 = Bs[(k + tig) * 68 + wn + j * 8 + gid];
                uint32_t b1 = Bs[(k + 4 + tig) * 68 + wn + j * 8 + gid];
                mma_tf32(acc[j][0], acc[j][1], acc[j][2], acc[j][3], a0, a1, a2, a3, b0, b1);
            }
        }
        __syncthreads();
    }
#pragma unroll
    for (int j = 0; j < 4; j++) {
        int n = n0 + wn + j * 8 + tig * 2;
        int m = m0 + wm + gid;
        float v0 = acc[j][0], v1 = acc[j][1], v2 = acc[j][2], v3 = acc[j][3];
        if (bias) { float b0 = bias[n], b1 = bias[n + 1]; v0 += b0; v1 += b1; v2 += b0; v3 += b1; }
        size_t o0 = (size_t)m * N + n, o1 = (size_t)(m + 8) * N + n;
        C[o0] = v0; C[o0 + 1] = v1; C[o1] = v2; C[o1 + 1] = v3;
    }
}

// ---------------- attention ----------------
__global__ void attn_kernel(const float* __restrict__ q, const float* __restrict__ k,
                            const float* __restrict__ v, float* __restrict__ ctx) {
    int bid = blockIdx.x;
    int qi = bid & (SEQ - 1);
    int h  = (bid >> 9) & (NHEAD - 1);
    int b  = bid >> 11;
    int t  = b * SEQ + qi;
    int tid = threadIdx.x, warp = tid >> 5, lane = tid & 31;
    __shared__ float sc[SEQ];
    __shared__ float qs[DHEAD];
    __shared__ float red[4];
    __shared__ float cbuf[DHEAD];

    if (tid < DHEAD) qs[tid] = q[t * 256 + h * 64 + tid];
    __syncthreads();
    int nk = qi + 1;
    for (int j = warp; j < nk; j += 4) {
        const float* kr = k + (b * SEQ + j) * 256 + h * 64;
        float p = qs[lane] * kr[lane] + qs[lane + 32] * kr[lane + 32];
#pragma unroll
        for (int o = 16; o; o >>= 1) p += __shfl_down_sync(0xffffffffu, p, o);
        if (!lane) sc[j] = p * 0.125f;
    }
    __syncthreads();
    float m = -1e30f;
    for (int j = tid; j < nk; j += 128) m = fmaxf(m, sc[j]);
#pragma unroll
    for (int o = 16; o; o >>= 1) m = fmaxf(m, __shfl_xor_sync(0xffffffffu, m, o));
    if (!lane) red[warp] = m;
    __syncthreads();
    m = fmaxf(fmaxf(red[0], red[1]), fmaxf(red[2], red[3]));
    __syncthreads();
    float ssum = 0.f;
    for (int j = tid; j < nk; j += 128) { float e = expf(sc[j] - m); sc[j] = e; ssum += e; }
#pragma unroll
    for (int o = 16; o; o >>= 1) ssum += __shfl_xor_sync(0xffffffffu, ssum, o);
    if (!lane) red[warp] = ssum;
    __syncthreads();
    float inv = 1.f / (red[0] + red[1] + red[2] + red[3]);
    int d = tid & 63, half = tid >> 6;
    float acc = 0.f;
    for (int j = half; j < nk; j += 2) acc += sc[j] * v[(b * SEQ + j) * 256 + h * 64 + d];
    if (!half) cbuf[d] = acc;
    __syncthreads();
    if (half) ctx[t * 256 + h * 64 + d] = (cbuf[d] + acc) * inv;
}

// ---------------- recipe softmax + neuron embeddings ----------------
__global__ void rsoft_kernel(const float* __restrict__ recipes, const float* __restrict__ basis,
                             float* __restrict__ Rsoft, float* __restrict__ nemb) {
    int tid = threadIdx.x;
    __shared__ float rs[NNEUR * NBASIS];
    if (tid < NNEUR) {
        float row[NBASIS];
        float mx = -1e30f;
        for (int nb = 0; nb < NBASIS; nb++) { row[nb] = recipes[tid * NBASIS + nb]; mx = fmaxf(mx, row[nb]); }
        float s = 0.f;
        for (int nb = 0; nb < NBASIS; nb++) { row[nb] = expf(row[nb] - mx); s += row[nb]; }
        float invs = 1.f / s;
        for (int nb = 0; nb < NBASIS; nb++) {
            float vv = row[nb] * invs;
            rs[tid * NBASIS + nb] = vv;
            Rsoft[tid * NBASIS + nb] = vv;
        }
    }
    __syncthreads();
    for (int i = tid; i < NNEUR * D_MODEL; i += 256) {
        int n = i >> 8, d = i & 255;
        float s = 0.f;
        for (int nb = 0; nb < NBASIS; nb++) s = fmaf(rs[n * NBASIS + nb], basis[nb * 256 + d], s);
        nemb[i] = s;
    }
}

// ---------------- neuron-core precompute: NC[n][e] = sum_nb Rsoft[n][nb]*src[nb][e] ----------------
__global__ void ncore_kernel(const float* __restrict__ Rsoft, const float* __restrict__ src,
                             float* __restrict__ dst, int esize) {
    __shared__ float rs[NNEUR * NBASIS];
    int tid = threadIdx.x;
    for (int i = tid; i < NNEUR * NBASIS; i += 256) rs[i] = Rsoft[i];
    __syncthreads();
    int e = blockIdx.x * 256 + tid;
    float v[NBASIS];
#pragma unroll
    for (int nb = 0; nb < NBASIS; nb++) v[nb] = src[nb * esize + e];
    for (int n = 0; n < NNEUR; n++) {
        float a = 0.f;
#pragma unroll
        for (int nb = 0; nb < NBASIS; nb++) a = fmaf(rs[n * NBASIS + nb], v[nb], a);
        dst[n * esize + e] = a;
    }
}

// ---------------- fused score + router (writes topk idx + weights) ----------------
__global__ void scorerouter_kernel(const float* __restrict__ query, const float* __restrict__ nemb,
                                   int* __restrict__ topi, float* __restrict__ topw) {
    int t = blockIdx.x;
    int tid = threadIdx.x, warp = tid >> 5, lane = tid & 31;
    __shared__ float qrow[256];
    __shared__ float sc[NNEUR];
    __shared__ int   idxs[TOPK];
    __shared__ float wv[TOPK];
    qrow[tid] = query[t * 256 + tid];
    __syncthreads();
#pragma unroll
    for (int u = 0; u < 8; u++) {
        int n = warp * 8 + u;
        const float* nr = nemb + n * 256;
        float acc = 0.f;
#pragma unroll
        for (int i = 0; i < 8; i++) acc = fmaf(qrow[lane + 32 * i], nr[lane + 32 * i], acc);
#pragma unroll
        for (int o = 16; o; o >>= 1) acc += __shfl_down_sync(0xffffffffu, acc, o);
        if (!lane) sc[n] = acc;
    }
    __syncthreads();
    if (tid == 0) {
        float vals[TOPK];
        for (int kk = 0; kk < TOPK; kk++) {
            float best = -1e30f; int bi = 0;
            for (int n = 0; n < NNEUR; n++) if (sc[n] > best) { best = sc[n]; bi = n; }
            vals[kk] = best; idxs[kk] = bi; sc[bi] = -1e30f;
        }
        float mx = vals[0];
        float e[TOPK], s = 0.f;
        for (int kk = 0; kk < TOPK; kk++) { e[kk] = expf(vals[kk] - mx); s += e[kk]; }
        float invs = 1.f / s;
        for (int kk = 0; kk < TOPK; kk++) wv[kk] = e[kk] * invs;
    }
    __syncthreads();
    if (tid < TOPK) {
        topi[t * TOPK + tid] = idxs[tid];
        topw[t * TOPK + tid] = wv[tid];
    }
}

// ---------------- TT FFN stage A (neuron gather, rank-split) ----------------
struct SmemA {
    float N1[NNEUR * 128];   // rank slice: [n][i(16)][k(8)]
    float N2[NNEUR * 128];   // rank slice: [n][j(16)][l(8)]
    float xf[16][256];
    float a1[16][128];
    float a2[16][128];
    float tr[16][128];
};

__global__ __launch_bounds__(512) void stageA_kernel(
        const float* __restrict__ nrm2, const int* __restrict__ topi, const float* __restrict__ topw,
        const float* __restrict__ NA1, const float* __restrict__ NA2,
        float* __restrict__ hpart) {
    extern __shared__ float smemraw[];
    SmemA& S = *reinterpret_cast<SmemA*>(smemraw);
    int tid = threadIdx.x, tg = tid >> 5, lane = tid & 31;
    int t0 = blockIdx.x * 16;
    int r0 = blockIdx.y * RPER;
#pragma unroll
    for (int u = tid; u < 1024; u += 512)
        ((float4*)S.xf)[u] = ((const float4*)(nrm2 + t0 * 256))[u];
    __syncthreads();
    int t = t0 + tg;
    int nid[TOPK]; float nw[TOPK];
#pragma unroll
    for (int kk = 0; kk < TOPK; kk++) { nid[kk] = topi[t * TOPK + kk]; nw[kk] = topw[t * TOPK + kk]; }
    float hacc0 = 0.f, hacc1 = 0.f;
    int o = lane * 4;

    for (int ri = 0; ri < RPER; ri++) {
        int r = r0 + ri;
        __syncthreads();
        // load neuron slices (2048 float4 each)
#pragma unroll
        for (int it = 0; it < 4; it++) {
            int u = tid + it * 512;
            int n = u >> 5, rest = u & 31;
            int i = rest >> 1, kq = (rest & 1) * 4;
            *(float4*)&S.N1[n * 128 + i * 8 + kq] =
                *(const float4*)&NA1[n * 8192 + i * 512 + r * 8 + kq];
            *(float4*)&S.N2[n * 128 + rest * 4] =
                *(const float4*)&NA2[n * 8192 + r * 128 + rest * 4];
        }
        __syncthreads();
        // mix from 8 neurons
        float m0 = 0, m1 = 0, m2 = 0, m3 = 0, p0 = 0, p1 = 0, p2 = 0, p3 = 0;
#pragma unroll
        for (int kk = 0; kk < TOPK; kk++) {
            float ww = nw[kk];
            const float* s1 = &S.N1[nid[kk] * 128 + o];
            const float* s2 = &S.N2[nid[kk] * 128 + o];
            m0 = fmaf(ww, s1[0], m0); m1 = fmaf(ww, s1[1], m1);
            m2 = fmaf(ww, s1[2], m2); m3 = fmaf(ww, s1[3], m3);
            p0 = fmaf(ww, s2[0], p0); p1 = fmaf(ww, s2[1], p1);
            p2 = fmaf(ww, s2[2], p2); p3 = fmaf(ww, s2[3], p3);
        }
        S.a1[tg][o] = m0; S.a1[tg][o + 1] = m1; S.a1[tg][o + 2] = m2; S.a1[tg][o + 3] = m3;
        S.a2[tg][o] = p0; S.a2[tg][o + 1] = p1; S.a2[tg][o + 2] = p2; S.a2[tg][o + 3] = p3;
        __syncwarp();
        // t[j,k] = sum_i xf[i,j]*a1[i,k]
#pragma unroll
        for (int qd = 0; qd < 4; qd++) {
            int idx = o + qd; int j = idx >> 3, kk = idx & 7;
            float s = 0.f;
#pragma unroll
            for (int i2 = 0; i2 < 16; i2++) s = fmaf(S.xf[tg][i2 * 16 + j], S.a1[tg][i2 * 8 + kk], s);
            S.tr[tg][idx] = s;
        }
        __syncwarp();
        // h[k,l] += sum_j t[j,k]*a2[j,l]
#pragma unroll
        for (int qd = 0; qd < 2; qd++) {
            int idx = lane * 2 + qd; int kk = idx >> 3, l = idx & 7;
            float s = 0.f;
#pragma unroll
            for (int j = 0; j < 16; j++) s = fmaf(S.tr[tg][j * 8 + kk], S.a2[tg][j * 8 + l], s);
            if (qd == 0) hacc0 += s; else hacc1 += s;
        }
    }
    hpart[(blockIdx.y * T_TOK + t) * 64 + lane * 2]     = hacc0;
    hpart[(blockIdx.y * T_TOK + t) * 64 + lane * 2 + 1] = hacc1;
}

__global__ void hreduce_kernel(const float* __restrict__ hpart, float* __restrict__ h) {
    int idx = blockIdx.x * 256 + threadIdx.x;
    float s = 0.f;
#pragma unroll
    for (int g = 0; g < RGROUPS; g++) s += hpart[g * (T_TOK * 64) + idx];
    h[idx] = s;
}

// ---------------- TT FFN stage B (neuron gather, rank-split) ----------------
struct SmemB {
    float N1[NNEUR * 256];   // rank slice: [n][i(8)][k(32)]
    float N2[NNEUR * 256];   // rank slice: [n][j(8)][l(32)]
    float tr[16][256];
    float hf[16][64];
};

__global__ __launch_bounds__(512) void stageB_kernel(
        const float* __restrict__ hin, const int* __restrict__ topi, const float* __restrict__ topw,
        const float* __restrict__ NB1, const float* __restrict__ NB2,
        float* __restrict__ ffnpart) {
    extern __shared__ float smemraw[];
    SmemB& S = *reinterpret_cast<SmemB*>(smemraw);
    int tid = threadIdx.x, tg = tid >> 5, lane = tid & 31;
    int t0 = blockIdx.x * 16;
    int r0 = blockIdx.y * RPER;
    for (int u = tid; u < 256; u += 512)
        ((float4*)S.hf)[u] = ((const float4*)(hin + t0 * 64))[u];
    __syncthreads();
    int t = t0 + tg;
    int nid[TOPK]; float nw[TOPK];
#pragma unroll
    for (int kk = 0; kk < TOPK; kk++) { nid[kk] = topi[t * TOPK + kk]; nw[kk] = topw[t * TOPK + kk]; }
    float oreg[32];
#pragma unroll
    for (int i = 0; i < 32; i++) oreg[i] = 0.f;

    for (int ri = 0; ri < RPER; ri++) {
        int r = r0 + ri;
        __syncthreads();
        // load neuron slices (4096 float4 each)
#pragma unroll
        for (int it = 0; it < 8; it++) {
            int u = tid + it * 512;
            int n = u >> 6, rest = u & 63;
            int i = rest >> 3, kq = (rest & 7) * 4;
            *(float4*)&S.N1[n * 256 + i * 32 + kq] =
                *(const float4*)&NB1[n * 16384 + i * 2048 + r * 32 + kq];
            *(float4*)&S.N2[n * 256 + rest * 4] =
                *(const float4*)&NB2[n * 16384 + r * 256 + rest * 4];
        }
        __syncthreads();
        // mix from 8 neurons (lane owns column k=lane / l=lane)
        float b1r[8], b2r[8];
#pragma unroll
        for (int i = 0; i < 8; i++) {
            float s1 = 0.f, s2 = 0.f;
#pragma unroll
            for (int kk = 0; kk < TOPK; kk++) {
                s1 = fmaf(nw[kk], S.N1[nid[kk] * 256 + i * 32 + lane], s1);
                s2 = fmaf(nw[kk], S.N2[nid[kk] * 256 + i * 32 + lane], s2);
            }
            b1r[i] = s1; b2r[i] = s2;
        }
        // t[j,k=lane] = sum_i hf[i,j]*b1[i,lane]
#pragma unroll
        for (int j = 0; j < 8; j++) {
            float s = 0.f;
#pragma unroll
            for (int i2 = 0; i2 < 8; i2++) s = fmaf(S.hf[tg][i2 * 8 + j], b1r[i2], s);
            S.tr[tg][j * 32 + lane] = s;
        }
        __syncwarp();
        // out[k,l=lane] += sum_j t[j,k]*b2[j,lane]
#pragma unroll
        for (int kk = 0; kk < 32; kk++) {
            float s = 0.f;
#pragma unroll
            for (int j = 0; j < 8; j++) s = fmaf(S.tr[tg][j * 32 + kk], b2r[j], s);
            oreg[kk] += s;
        }
        __syncwarp();
    }
    float* dst = ffnpart + (blockIdx.y * T_TOK + t) * (size_t)DFF;
#pragma unroll
    for (int kk = 0; kk < 32; kk++) dst[kk * 32 + lane] = oreg[kk];
}

__global__ void gelu_reduce_kernel(const float* __restrict__ ffnpart, float* __restrict__ ffn) {
    int idx = blockIdx.x * 256 + threadIdx.x;
    float s = 0.f;
#pragma unroll
    for (int g = 0; g < RGROUPS; g++) s += ffnpart[g * (size_t)(T_TOK * DFF) + idx];
    ffn[idx] = 0.5f * s * (1.f + erff(s * 0.70710678118654752f));
}

// ---------------- host orchestration ----------------
extern "C" void kernel_launch(void* const* d_in, const int* in_sizes, int n_in,
                              void* d_out, int out_size) {
    const int*   ids    = (const int*)d_in[0];
    const float* te     = (const float*)d_in[1];
    const float* pe     = (const float*)d_in[2];
    const float* qW     = (const float*)d_in[3];
    const float* qb     = (const float*)d_in[4];
    const float* kW     = (const float*)d_in[5];
    const float* kb     = (const float*)d_in[6];
    const float* vW     = (const float*)d_in[7];
    const float* vb     = (const float*)d_in[8];
    const float* sW     = (const float*)d_in[9];
    const float* sb     = (const float*)d_in[10];
    const float* recipes= (const float*)d_in[11];
    const float* wdW    = (const float*)d_in[12];
    const float* wdb    = (const float*)d_in[13];
    const float* n1g    = (const float*)d_in[14];
    const float* n1b    = (const float*)d_in[15];
    const float* n2g    = (const float*)d_in[16];
    const float* n2b    = (const float*)d_in[17];
    const float* basis  = (const float*)d_in[18];
    const float* A1     = (const float*)d_in[19];
    const float* A2     = (const float*)d_in[20];
    const float* B1     = (const float*)d_in[21];
    const float* B2     = (const float*)d_in[22];
    const float* fng    = (const float*)d_in[23];
    const float* fnb    = (const float*)d_in[24];
    float* out = (float*)d_out;

    float *x, *nrm1, *q, *k, *v, *ctx, *query, *nrm2, *h, *ffn, *Rsoft, *nemb, *hpart, *ffnpart;
    float *NA1, *NA2, *NB1, *NB2, *topw;
    int* topi;
    cudaGetSymbolAddress((void**)&x, g_x);
    cudaGetSymbolAddress((void**)&nrm1, g_nrm1);
    cudaGetSymbolAddress((void**)&q, g_q);
    cudaGetSymbolAddress((void**)&k, g_k);
    cudaGetSymbolAddress((void**)&v, g_v);
    cudaGetSymbolAddress((void**)&ctx, g_ctx);
    cudaGetSymbolAddress((void**)&query, g_query);
    cudaGetSymbolAddress((void**)&nrm2, g_nrm2);
    cudaGetSymbolAddress((void**)&h, g_h);
    cudaGetSymbolAddress((void**)&ffn, g_ffn);
    cudaGetSymbolAddress((void**)&Rsoft, g_Rsoft);
    cudaGetSymbolAddress((void**)&nemb, g_nemb);
    cudaGetSymbolAddress((void**)&hpart, g_hpart);
    cudaGetSymbolAddress((void**)&ffnpart, g_ffnpart);
    cudaGetSymbolAddress((void**)&NA1, g_NA1);
    cudaGetSymbolAddress((void**)&NA2, g_NA2);
    cudaGetSymbolAddress((void**)&NB1, g_NB1);
    cudaGetSymbolAddress((void**)&NB2, g_NB2);
    cudaGetSymbolAddress((void**)&topi, g_topi);
    cudaGetSymbolAddress((void**)&topw, g_topw);

    cudaFuncSetAttribute(stageA_kernel, cudaFuncAttributeMaxDynamicSharedMemorySize, (int)sizeof(SmemA));
    cudaFuncSetAttribute(stageB_kernel, cudaFuncAttributeMaxDynamicSharedMemorySize, (int)sizeof(SmemB));

    embed_kernel<<<T_TOK, 256>>>(ids, te, pe, x);

    dim3 g44(4, 16);
    for (int l = 0; l < NLAYER; l++) {
        ln_kernel<<<T_TOK, 256>>>(x, n1g + l * 256, n1b + l * 256, nrm1);
        W4 gb;
        gb.W[0] = qW + l * 65536;  gb.bias[0] = qb + l * 256; gb.out[0] = q;
        gb.W[1] = kW + l * 65536;  gb.bias[1] = kb + l * 256; gb.out[1] = k;
        gb.W[2] = vW + l * 65536;  gb.bias[2] = vb + l * 256; gb.out[2] = v;
        gb.W[3] = sW + l * 131072; gb.bias[3] = nullptr;      gb.out[3] = query;
        tc_gemmb<<<dim3(4, 16, 4), 256>>>(nrm1, gb, 1024, 256, 256);
        attn_kernel<<<T_TOK * NHEAD, 128>>>(q, k, v, ctx);
        tc_gemm<0><<<g44, 256>>>(ctx, sW + l * 131072 + 65536, sb + l * 256, query, 1024, 256, 256, 1.f);
        rsoft_kernel<<<1, 256>>>(recipes + l * 2048, basis, Rsoft, nemb);
        ncore_kernel<<<32, 256>>>(Rsoft, A1, NA1, 8192);
        ncore_kernel<<<32, 256>>>(Rsoft, A2, NA2, 8192);
        ncore_kernel<<<64, 256>>>(Rsoft, B1, NB1, 16384);
        ncore_kernel<<<64, 256>>>(Rsoft, B2, NB2, 16384);
        scorerouter_kernel<<<T_TOK, 256>>>(query, nemb, topi, topw);
        ln_kernel<<<T_TOK, 256>>>(x, n2g + l * 256, n2b + l * 256, nrm2);
        stageA_kernel<<<dim3(64, RGROUPS), 512, sizeof(SmemA)>>>(nrm2, topi, topw, NA1, NA2, hpart);
        hreduce_kernel<<<T_TOK * 64 / 256, 256>>>(hpart, h);
        stageB_kernel<<<dim3(64, RGROUPS), 512, sizeof(SmemB)>>>(h, topi, topw, NB1, NB2, ffnpart);
        gelu_reduce_kernel<<<T_TOK * DFF / 256, 256>>>(ffnpart, ffn);
        tc_gemm<0><<<g44, 256>>>(ffn, wdW + l * 262144, wdb + l * 256, x, 1024, 256, 1024, 1.f);
    }
    ln_kernel<<<T_TOK, 256>>>(x, fng, fnb, nrm1);
    tc_gemm<1><<<dim3(VOCAB / 64, 16), 256>>>(nrm1, te, nullptr, out, 1024, VOCAB, 256, 0.f);
}

// round 5
// speedup vs baseline: 2.3793x; 1.3432x over previous
#include <cuda_runtime.h>
#include <cuda_bf16.h>
#include <math.h>
#include <stdint.h>

// ---------------- constants ----------------
#define T_TOK   1024
#define D_MODEL 256
#define SEQ     512
#define NHEAD   4
#define DHEAD   64
#define NBASIS  32
#define RRANK   64
#define NNEUR   64
#define TOPK    8
#define DFF     1024
#define NLAYER  4
#define VOCAB   32000
#define TPB_A   32
#define RG_A    8
#define RPER_A  (RRANK / RG_A)
#define TPB_B   32
#define RG_B    4
#define RPER_B  (RRANK / RG_B)

// ---------------- scratch ----------------
__device__ float g_x[T_TOK * D_MODEL];
__device__ float g_nrm1[T_TOK * D_MODEL];
__device__ float g_q[T_TOK * D_MODEL];
__device__ float g_k[T_TOK * D_MODEL];
__device__ float g_v[T_TOK * D_MODEL];
__device__ float g_ctx[T_TOK * D_MODEL];
__device__ float g_query[T_TOK * D_MODEL];
__device__ float g_nrm2[T_TOK * D_MODEL];
__device__ float g_h[T_TOK * 64];          // unused now but kept
__device__ float g_ffn[T_TOK * DFF];
__device__ float g_Rsoft[NNEUR * NBASIS];
__device__ float g_nemb[NNEUR * D_MODEL];
__device__ float g_hpart[RG_A * T_TOK * 64];
__device__ float g_ffnpart[RG_B * T_TOK * DFF];
__device__ float g_wdpart[2 * T_TOK * D_MODEL];
__device__ int   g_topi[T_TOK * TOPK];
__device__ float g_topw[T_TOK * TOPK];
__device__ float g_NA1[NNEUR * 8192];   // [n][i(16)][r(64)][k(8)]
__device__ float g_NA2[NNEUR * 8192];   // [n][r(64)][j(16)][l(8)]
__device__ float g_NB1[NNEUR * 16384];  // [n][i(8)][r(64)][k(32)]
__device__ float g_NB2[NNEUR * 16384];  // [n][r(64)][j(8)][l(32)]

// ---------------- tf32 helpers ----------------
__device__ __forceinline__ uint32_t f2tf32(float f) {
    uint32_t u;
    asm("cvt.rna.tf32.f32 %0, %1;" : "=r"(u) : "f"(f));
    return u;
}
__device__ __forceinline__ void mma_tf32(float& c0, float& c1, float& c2, float& c3,
                                         uint32_t a0, uint32_t a1, uint32_t a2, uint32_t a3,
                                         uint32_t b0, uint32_t b1) {
    asm("mma.sync.aligned.m16n8k8.row.col.f32.tf32.tf32.f32 "
        "{%0,%1,%2,%3},{%4,%5,%6,%7},{%8,%9},{%0,%1,%2,%3};"
        : "+f"(c0), "+f"(c1), "+f"(c2), "+f"(c3)
        : "r"(a0), "r"(a1), "r"(a2), "r"(a3), "r"(b0), "r"(b1));
}

// ---------------- embed ----------------
__global__ void embed_kernel(const int* __restrict__ ids, const float* __restrict__ te,
                             const float* __restrict__ pe, float* __restrict__ x) {
    int t = blockIdx.x, d = threadIdx.x;
    int s = t & (SEQ - 1);
    x[t * 256 + d] = te[ids[t] * 256 + d] + pe[s * 256 + d];
}

// ---------------- layernorm ----------------
__global__ void ln_kernel(const float* __restrict__ x, const float* __restrict__ g,
                          const float* __restrict__ b, float* __restrict__ out) {
    int t = blockIdx.x, d = threadIdx.x;
    __shared__ float red[256];
    float v = x[t * 256 + d];
    red[d] = v;
    __syncthreads();
    for (int s = 128; s > 0; s >>= 1) { if (d < s) red[d] += red[d + s]; __syncthreads(); }
    float mean = red[0] * (1.f / 256.f);
    __syncthreads();
    float c = v - mean;
    red[d] = c * c;
    __syncthreads();
    for (int s = 128; s > 0; s >>= 1) { if (d < s) red[d] += red[d + s]; __syncthreads(); }
    float var = red[0] * (1.f / 256.f);
    out[t * 256 + d] = c * rsqrtf(var + 1e-5f) * g[d] + b[d];
}

// ---------------- tf32 GEMM 64x64 tile: C = A@B (+bias)(+beta*C), B [K,N] ----------------
__global__ __launch_bounds__(256) void tc_gemm(const float* __restrict__ A,
                                               const float* __restrict__ B,
                                               const float* __restrict__ bias,
                                               float* __restrict__ C,
                                               int M, int N, int K, float beta) {
    __shared__ uint32_t As[32 * 68];
    __shared__ uint32_t Bs[32 * 68];
    int tid = threadIdx.x, lane = tid & 31, wid = tid >> 5;
    int wm = (wid & 3) * 16, wn = (wid >> 2) * 32;
    int m0 = blockIdx.y * 64, n0 = blockIdx.x * 64;
    int gid = lane >> 2, tig = lane & 3;
    float acc[4][4];
#pragma unroll
    for (int j = 0; j < 4; j++)
#pragma unroll
        for (int i = 0; i < 4; i++) acc[j][i] = 0.f;

    for (int k0 = 0; k0 < K; k0 += 32) {
#pragma unroll
        for (int it = 0; it < 2; it++) {
            int u = tid + it * 256;
            int row = u >> 3, kq = (u & 7) * 4;
            float4 v = *(const float4*)&A[(size_t)(m0 + row) * K + k0 + kq];
            As[(kq + 0) * 68 + row] = f2tf32(v.x);
            As[(kq + 1) * 68 + row] = f2tf32(v.y);
            As[(kq + 2) * 68 + row] = f2tf32(v.z);
            As[(kq + 3) * 68 + row] = f2tf32(v.w);
        }
#pragma unroll
        for (int it = 0; it < 2; it++) {
            int u = tid + it * 256;
            int kb = u >> 4, nq = (u & 15) * 4;
            float4 v = *(const float4*)&B[(size_t)(k0 + kb) * N + n0 + nq];
            Bs[kb * 68 + nq + 0] = f2tf32(v.x);
            Bs[kb * 68 + nq + 1] = f2tf32(v.y);
            Bs[kb * 68 + nq + 2] = f2tf32(v.z);
            Bs[kb * 68 + nq + 3] = f2tf32(v.w);
        }
        __syncthreads();
#pragma unroll
        for (int s = 0; s < 4; s++) {
            int k = s * 8;
            uint32_t a0 = As[(k + tig) * 68 + wm + gid];
            uint32_t a1 = As[(k + tig) * 68 + wm + gid + 8];
            uint32_t a2 = As[(k + 4 + tig) * 68 + wm + gid];
            uint32_t a3 = As[(k + 4 + tig) * 68 + wm + gid + 8];
#pragma unroll
            for (int j = 0; j < 4; j++) {
                uint32_t b0 = Bs[(k + tig) * 68 + wn + j * 8 + gid];
                uint32_t b1 = Bs[(k + 4 + tig) * 68 + wn + j * 8 + gid];
                mma_tf32(acc[j][0], acc[j][1], acc[j][2], acc[j][3], a0, a1, a2, a3, b0, b1);
            }
        }
        __syncthreads();
    }
#pragma unroll
    for (int j = 0; j < 4; j++) {
        int n = n0 + wn + j * 8 + tig * 2;
        int m = m0 + wm + gid;
        float v0 = acc[j][0], v1 = acc[j][1], v2 = acc[j][2], v3 = acc[j][3];
        if (bias) { float b0 = bias[n], b1 = bias[n + 1]; v0 += b0; v1 += b1; v2 += b0; v3 += b1; }
        size_t o0 = (size_t)m * N + n, o1 = (size_t)(m + 8) * N + n;
        if (beta != 0.f) { v0 += C[o0]; v1 += C[o0 + 1]; v2 += C[o1]; v3 += C[o1 + 1]; }
        C[o0] = v0; C[o0 + 1] = v1; C[o1] = v2; C[o1 + 1] = v3;
    }
}

// ---------------- split-K tf32 GEMM: partial z-buffer out ----------------
__global__ __launch_bounds__(256) void tc_gemm_sk(const float* __restrict__ A,
                                                  const float* __restrict__ B,
                                                  float* __restrict__ Cpart,
                                                  int N, int K, int klen) {
    __shared__ uint32_t As[32 * 68];
    __shared__ uint32_t Bs[32 * 68];
    int tid = threadIdx.x, lane = tid & 31, wid = tid >> 5;
    int wm = (wid & 3) * 16, wn = (wid >> 2) * 32;
    int m0 = blockIdx.y * 64, n0 = blockIdx.x * 64;
    int gid = lane >> 2, tig = lane & 3;
    int kbeg = blockIdx.z * klen;
    float* C = Cpart + (size_t)blockIdx.z * T_TOK * D_MODEL;
    float acc[4][4];
#pragma unroll
    for (int j = 0; j < 4; j++)
#pragma unroll
        for (int i = 0; i < 4; i++) acc[j][i] = 0.f;

    for (int k0 = kbeg; k0 < kbeg + klen; k0 += 32) {
#pragma unroll
        for (int it = 0; it < 2; it++) {
            int u = tid + it * 256;
            int row = u >> 3, kq = (u & 7) * 4;
            float4 v = *(const float4*)&A[(size_t)(m0 + row) * K + k0 + kq];
            As[(kq + 0) * 68 + row] = f2tf32(v.x);
            As[(kq + 1) * 68 + row] = f2tf32(v.y);
            As[(kq + 2) * 68 + row] = f2tf32(v.z);
            As[(kq + 3) * 68 + row] = f2tf32(v.w);
        }
#pragma unroll
        for (int it = 0; it < 2; it++) {
            int u = tid + it * 256;
            int kb = u >> 4, nq = (u & 15) * 4;
            float4 v = *(const float4*)&B[(size_t)(k0 + kb) * N + n0 + nq];
            Bs[kb * 68 + nq + 0] = f2tf32(v.x);
            Bs[kb * 68 + nq + 1] = f2tf32(v.y);
            Bs[kb * 68 + nq + 2] = f2tf32(v.z);
            Bs[kb * 68 + nq + 3] = f2tf32(v.w);
        }
        __syncthreads();
#pragma unroll
        for (int s = 0; s < 4; s++) {
            int k = s * 8;
            uint32_t a0 = As[(k + tig) * 68 + wm + gid];
            uint32_t a1 = As[(k + tig) * 68 + wm + gid + 8];
            uint32_t a2 = As[(k + 4 + tig) * 68 + wm + gid];
            uint32_t a3 = As[(k + 4 + tig) * 68 + wm + gid + 8];
#pragma unroll
            for (int j = 0; j < 4; j++) {
                uint32_t b0 = Bs[(k + tig) * 68 + wn + j * 8 + gid];
                uint32_t b1 = Bs[(k + 4 + tig) * 68 + wn + j * 8 + gid];
                mma_tf32(acc[j][0], acc[j][1], acc[j][2], acc[j][3], a0, a1, a2, a3, b0, b1);
            }
        }
        __syncthreads();
    }
#pragma unroll
    for (int j = 0; j < 4; j++) {
        int n = n0 + wn + j * 8 + tig * 2;
        int m = m0 + wm + gid;
        size_t o0 = (size_t)m * N + n, o1 = (size_t)(m + 8) * N + n;
        C[o0] = acc[j][0]; C[o0 + 1] = acc[j][1]; C[o1] = acc[j][2]; C[o1 + 1] = acc[j][3];
    }
}

__global__ void wdadd_kernel(const float* __restrict__ p, const float* __restrict__ bias,
                             float* __restrict__ x) {
    int idx = blockIdx.x * 256 + threadIdx.x;
    x[idx] += p[idx] + p[T_TOK * D_MODEL + idx] + bias[idx & 255];
}

// ---------------- batched tf32 GEMM (4 weights, shared A, B [K,N]) ----------------
struct W4 { const float* W[4]; const float* bias[4]; float* out[4]; };

__global__ __launch_bounds__(256) void tc_gemmb(const float* __restrict__ A, W4 gb,
                                                int M, int N, int K) {
    const float* __restrict__ B = gb.W[blockIdx.z];
    const float* __restrict__ bias = gb.bias[blockIdx.z];
    float* __restrict__ C = gb.out[blockIdx.z];
    __shared__ uint32_t As[32 * 68];
    __shared__ uint32_t Bs[32 * 68];
    int tid = threadIdx.x, lane = tid & 31, wid = tid >> 5;
    int wm = (wid & 3) * 16, wn = (wid >> 2) * 32;
    int m0 = blockIdx.y * 64, n0 = blockIdx.x * 64;
    int gid = lane >> 2, tig = lane & 3;
    float acc[4][4];
#pragma unroll
    for (int j = 0; j < 4; j++)
#pragma unroll
        for (int i = 0; i < 4; i++) acc[j][i] = 0.f;

    for (int k0 = 0; k0 < K; k0 += 32) {
#pragma unroll
        for (int it = 0; it < 2; it++) {
            int u = tid + it * 256;
            int row = u >> 3, kq = (u & 7) * 4;
            float4 v = *(const float4*)&A[(size_t)(m0 + row) * K + k0 + kq];
            As[(kq + 0) * 68 + row] = f2tf32(v.x);
            As[(kq + 1) * 68 + row] = f2tf32(v.y);
            As[(kq + 2) * 68 + row] = f2tf32(v.z);
            As[(kq + 3) * 68 + row] = f2tf32(v.w);
        }
#pragma unroll
        for (int it = 0; it < 2; it++) {
            int u = tid + it * 256;
            int kb = u >> 4, nq = (u & 15) * 4;
            float4 v = *(const float4*)&B[(size_t)(k0 + kb) * N + n0 + nq];
            Bs[kb * 68 + nq + 0] = f2tf32(v.x);
            Bs[kb * 68 + nq + 1] = f2tf32(v.y);
            Bs[kb * 68 + nq + 2] = f2tf32(v.z);
            Bs[kb * 68 + nq + 3] = f2tf32(v.w);
        }
        __syncthreads();
#pragma unroll
        for (int s = 0; s < 4; s++) {
            int k = s * 8;
            uint32_t a0 = As[(k + tig) * 68 + wm + gid];
            uint32_t a1 = As[(k + tig) * 68 + wm + gid + 8];
            uint32_t a2 = As[(k + 4 + tig) * 68 + wm + gid];
            uint32_t a3 = As[(k + 4 + tig) * 68 + wm + gid + 8];
#pragma unroll
            for (int j = 0; j < 4; j++) {
                uint32_t b0 = Bs[(k + tig) * 68 + wn + j * 8 + gid];
                uint32_t b1 = Bs[(k + 4 + tig) * 68 + wn + j * 8 + gid];
                mma_tf32(acc[j][0], acc[j][1], acc[j][2], acc[j][3], a0, a1, a2, a3, b0, b1);
            }
        }
        __syncthreads();
    }
#pragma unroll
    for (int j = 0; j < 4; j++) {
        int n = n0 + wn + j * 8 + tig * 2;
        int m = m0 + wm + gid;
        float v0 = acc[j][0], v1 = acc[j][1], v2 = acc[j][2], v3 = acc[j][3];
        if (bias) { float b0 = bias[n], b1 = bias[n + 1]; v0 += b0; v1 += b1; v2 += b0; v3 += b1; }
        size_t o0 = (size_t)m * N + n, o1 = (size_t)(m + 8) * N + n;
        C[o0] = v0; C[o0 + 1] = v1; C[o1] = v2; C[o1 + 1] = v3;
    }
}

// ---------------- head GEMM 128x64 tile: C = A @ B^T, B [N,K] row-major ----------------
__global__ __launch_bounds__(256) void hg_kernel(const float* __restrict__ A,
                                                 const float* __restrict__ B,
                                                 float* __restrict__ C,
                                                 int M, int N, int K) {
    __shared__ uint32_t As[32 * 132];
    __shared__ uint32_t Bs[32 * 68];
    int tid = threadIdx.x, lane = tid & 31, wid = tid >> 5;
    int wm = (wid & 3) * 32, wn = (wid >> 2) * 32;
    int m0 = blockIdx.y * 128, n0 = blockIdx.x * 64;
    int gid = lane >> 2, tig = lane & 3;
    float acc[2][4][4];
#pragma unroll
    for (int mb = 0; mb < 2; mb++)
#pragma unroll
        for (int j = 0; j < 4; j++)
#pragma unroll
            for (int i = 0; i < 4; i++) acc[mb][j][i] = 0.f;

    for (int k0 = 0; k0 < K; k0 += 32) {
#pragma unroll
        for (int it = 0; it < 4; it++) {
            int u = tid + it * 256;
            int row = u >> 3, kq = (u & 7) * 4;
            float4 v = *(const float4*)&A[(size_t)(m0 + row) * K + k0 + kq];
            As[(kq + 0) * 132 + row] = f2tf32(v.x);
            As[(kq + 1) * 132 + row] = f2tf32(v.y);
            As[(kq + 2) * 132 + row] = f2tf32(v.z);
            As[(kq + 3) * 132 + row] = f2tf32(v.w);
        }
#pragma unroll
        for (int it = 0; it < 2; it++) {
            int u = tid + it * 256;
            int row = u >> 3, kq = (u & 7) * 4;
            float4 v = *(const float4*)&B[(size_t)(n0 + row) * K + k0 + kq];
            Bs[(kq + 0) * 68 + row] = f2tf32(v.x);
            Bs[(kq + 1) * 68 + row] = f2tf32(v.y);
            Bs[(kq + 2) * 68 + row] = f2tf32(v.z);
            Bs[(kq + 3) * 68 + row] = f2tf32(v.w);
        }
        __syncthreads();
#pragma unroll
        for (int s = 0; s < 4; s++) {
            int k = s * 8;
            uint32_t a[2][4];
#pragma unroll
            for (int mb = 0; mb < 2; mb++) {
                int mo = wm + mb * 16;
                a[mb][0] = As[(k + tig) * 132 + mo + gid];
                a[mb][1] = As[(k + tig) * 132 + mo + gid + 8];
                a[mb][2] = As[(k + 4 + tig) * 132 + mo + gid];
                a[mb][3] = As[(k + 4 + tig) * 132 + mo + gid + 8];
            }
#pragma unroll
            for (int j = 0; j < 4; j++) {
                uint32_t b0 = Bs[(k + tig) * 68 + wn + j * 8 + gid];
                uint32_t b1 = Bs[(k + 4 + tig) * 68 + wn + j * 8 + gid];
#pragma unroll
                for (int mb = 0; mb < 2; mb++)
                    mma_tf32(acc[mb][j][0], acc[mb][j][1], acc[mb][j][2], acc[mb][j][3],
                             a[mb][0], a[mb][1], a[mb][2], a[mb][3], b0, b1);
            }
        }
        __syncthreads();
    }
#pragma unroll
    for (int mb = 0; mb < 2; mb++)
#pragma unroll
        for (int j = 0; j < 4; j++) {
            int n = n0 + wn + j * 8 + tig * 2;
            int m = m0 + wm + mb * 16 + gid;
            size_t o0 = (size_t)m * N + n, o1 = (size_t)(m + 8) * N + n;
            C[o0] = acc[mb][j][0]; C[o0 + 1] = acc[mb][j][1];
            C[o1] = acc[mb][j][2]; C[o1 + 1] = acc[mb][j][3];
        }
}

// ---------------- flash attention (tf32): qtile=32, block 128 threads ----------------
// grid (SEQ/32=16, B*H=8). smem: Ps[32][520] + Ks[64][68] + Qs[32][68]
#define FA_SMEM ((32 * 520 + 64 * 68 + 32 * 68) * 4)
__global__ __launch_bounds__(128) void fattn_kernel(const float* __restrict__ q,
                                                    const float* __restrict__ k,
                                                    const float* __restrict__ v,
                                                    float* __restrict__ ctx) {
    extern __shared__ float sm[];
    float* Ps = sm;                       // [32][520]
    float* Ks = sm + 32 * 520;            // [64][68] (K, then reused for V)
    float* Qs = Ks + 64 * 68;             // [32][68]
    int qt = blockIdx.x;
    int bh = blockIdx.y;
    int b = bh >> 2, h = bh & 3;
    int tid = threadIdx.x, w = tid >> 5, lane = tid & 31;
    int gid = lane >> 2, tig = lane & 3;
    int r0 = (w & 1) * 16, nh = w >> 1;
    int q0 = qt * 32;
    int ktmax = (q0 + 95) / 64;

    // load Q tile
    for (int u = tid; u < 512; u += 128) {
        int row = u >> 4, dq = (u & 15) * 4;
        float4 t4 = *(const float4*)&q[(size_t)(b * SEQ + q0 + row) * 256 + h * 64 + dq];
        Qs[row * 68 + dq] = t4.x; Qs[row * 68 + dq + 1] = t4.y;
        Qs[row * 68 + dq + 2] = t4.z; Qs[row * 68 + dq + 3] = t4.w;
    }
    __syncthreads();
    uint32_t qa[8][4];
#pragma unroll
    for (int kb = 0; kb < 8; kb++) {
        qa[kb][0] = f2tf32(Qs[(r0 + gid) * 68 + kb * 8 + tig]);
        qa[kb][1] = f2tf32(Qs[(r0 + gid + 8) * 68 + kb * 8 + tig]);
        qa[kb][2] = f2tf32(Qs[(r0 + gid) * 68 + kb * 8 + tig + 4]);
        qa[kb][3] = f2tf32(Qs[(r0 + gid + 8) * 68 + kb * 8 + tig + 4]);
    }
    // phase 1: scores
    for (int kt = 0; kt < ktmax; kt++) {
        __syncthreads();
        for (int u = tid; u < 1024; u += 128) {
            int row = u >> 4, dq = (u & 15) * 4;
            float4 t4 = *(const float4*)&k[(size_t)(b * SEQ + kt * 64 + row) * 256 + h * 64 + dq];
            Ks[row * 68 + dq] = t4.x; Ks[row * 68 + dq + 1] = t4.y;
            Ks[row * 68 + dq + 2] = t4.z; Ks[row * 68 + dq + 3] = t4.w;
        }
        __syncthreads();
#pragma unroll
        for (int jb = 0; jb < 4; jb++) {
            float c0 = 0.f, c1 = 0.f, c2 = 0.f, c3 = 0.f;
#pragma unroll
            for (int kb = 0; kb < 8; kb++) {
                uint32_t b0 = f2tf32(Ks[(nh * 32 + jb * 8 + gid) * 68 + kb * 8 + tig]);
                uint32_t b1 = f2tf32(Ks[(nh * 32 + jb * 8 + gid) * 68 + kb * 8 + tig + 4]);
                mma_tf32(c0, c1, c2, c3, qa[kb][0], qa[kb][1], qa[kb][2], qa[kb][3], b0, b1);
            }
            int qg0 = q0 + r0 + gid, qg1 = qg0 + 8;
            int kg = kt * 64 + nh * 32 + jb * 8 + 2 * tig;
            Ps[(r0 + gid) * 520 + kg]     = (kg     <= qg0) ? c0 * 0.125f : -1e30f;
            Ps[(r0 + gid) * 520 + kg + 1] = (kg + 1 <= qg0) ? c1 * 0.125f : -1e30f;
            Ps[(r0 + gid + 8) * 520 + kg]     = (kg     <= qg1) ? c2 * 0.125f : -1e30f;
            Ps[(r0 + gid + 8) * 520 + kg + 1] = (kg + 1 <= qg1) ? c3 * 0.125f : -1e30f;
        }
    }
    __syncthreads();
    // phase 2: row softmax
    {
        int row = w * 8 + (lane >> 2);
        int c0i = lane & 3;
        int ncols = ktmax * 64;
        float m = -1e30f;
        for (int c = c0i; c < ncols; c += 4) m = fmaxf(m, Ps[row * 520 + c]);
        m = fmaxf(m, __shfl_xor_sync(0xffffffffu, m, 1));
        m = fmaxf(m, __shfl_xor_sync(0xffffffffu, m, 2));
        float s = 0.f;
        for (int c = c0i; c < ncols; c += 4) {
            float e = expf(Ps[row * 520 + c] - m);
            Ps[row * 520 + c] = e;
            s += e;
        }
        s += __shfl_xor_sync(0xffffffffu, s, 1);
        s += __shfl_xor_sync(0xffffffffu, s, 2);
        float inv = 1.f / s;
        for (int c = c0i; c < ncols; c += 4) Ps[row * 520 + c] *= inv;
    }
    __syncthreads();
    // phase 3: O = P @ V
    float oacc[4][4];
#pragma unroll
    for (int j = 0; j < 4; j++)
#pragma unroll
        for (int i = 0; i < 4; i++) oacc[j][i] = 0.f;
    for (int kt = 0; kt < ktmax; kt++) {
        for (int u = tid; u < 1024; u += 128) {
            int row = u >> 4, dq = (u & 15) * 4;
            float4 t4 = *(const float4*)&v[(size_t)(b * SEQ + kt * 64 + row) * 256 + h * 64 + dq];
            Ks[row * 68 + dq] = t4.x; Ks[row * 68 + dq + 1] = t4.y;
            Ks[row * 68 + dq + 2] = t4.z; Ks[row * 68 + dq + 3] = t4.w;
        }
        __syncthreads();
#pragma unroll
        for (int kb = 0; kb < 8; kb++) {
            uint32_t a0 = f2tf32(Ps[(r0 + gid) * 520 + kt * 64 + kb * 8 + tig]);
            uint32_t a1 = f2tf32(Ps[(r0 + gid + 8) * 520 + kt * 64 + kb * 8 + tig]);
            uint32_t a2 = f2tf32(Ps[(r0 + gid) * 520 + kt * 64 + kb * 8 + tig + 4]);
            uint32_t a3 = f2tf32(Ps[(r0 + gid + 8) * 520 + kt * 64 + kb * 8 + tig + 4]);
#pragma unroll
            for (int jb = 0; jb < 4; jb++) {
                uint32_t b0 = f2tf32(Ks[(kb * 8 + tig) * 68 + nh * 32 + jb * 8 + gid]);
                uint32_t b1 = f2tf32(Ks[(kb * 8 + 4 + tig) * 68 + nh * 32 + jb * 8 + gid]);
                mma_tf32(oacc[jb][0], oacc[jb][1], oacc[jb][2], oacc[jb][3], a0, a1, a2, a3, b0, b1);
            }
        }
        __syncthreads();
    }
#pragma unroll
    for (int jb = 0; jb < 4; jb++) {
        int n = h * 64 + nh * 32 + jb * 8 + 2 * tig;
        size_t mrow = (size_t)(b * SEQ + q0 + r0 + gid);
        ctx[mrow * 256 + n] = oacc[jb][0];
        ctx[mrow * 256 + n + 1] = oacc[jb][1];
        ctx[(mrow + 8) * 256 + n] = oacc[jb][2];
        ctx[(mrow + 8) * 256 + n + 1] = oacc[jb][3];
    }
}

// ---------------- recipe softmax + neuron embeddings ----------------
__global__ void rsoft_kernel(const float* __restrict__ recipes, const float* __restrict__ basis,
                             float* __restrict__ Rsoft, float* __restrict__ nemb) {
    int tid = threadIdx.x;
    __shared__ float rs[NNEUR * NBASIS];
    if (tid < NNEUR) {
        float row[NBASIS];
        float mx = -1e30f;
        for (int nb = 0; nb < NBASIS; nb++) { row[nb] = recipes[tid * NBASIS + nb]; mx = fmaxf(mx, row[nb]); }
        float s = 0.f;
        for (int nb = 0; nb < NBASIS; nb++) { row[nb] = expf(row[nb] - mx); s += row[nb]; }
        float invs = 1.f / s;
        for (int nb = 0; nb < NBASIS; nb++) {
            float vv = row[nb] * invs;
            rs[tid * NBASIS + nb] = vv;
            Rsoft[tid * NBASIS + nb] = vv;
        }
    }
    __syncthreads();
    for (int i = tid; i < NNEUR * D_MODEL; i += 256) {
        int n = i >> 8, d = i & 255;
        float s = 0.f;
        for (int nb = 0; nb < NBASIS; nb++) s = fmaf(rs[n * NBASIS + nb], basis[nb * 256 + d], s);
        nemb[i] = s;
    }
}

// ---------------- fused neuron-core precompute (4 arrays, one launch) ----------------
struct NCJ { const float* src; float* dst; int esize; };
__global__ void ncore4_kernel(const float* __restrict__ Rsoft, NCJ j0, NCJ j1, NCJ j2, NCJ j3) {
    __shared__ float rs[NNEUR * NBASIS];
    int tid = threadIdx.x;
    for (int i = tid; i < NNEUR * NBASIS; i += 256) rs[i] = Rsoft[i];
    __syncthreads();
    NCJ j = (blockIdx.y == 0) ? j0 : (blockIdx.y == 1) ? j1 : (blockIdx.y == 2) ? j2 : j3;
    int e = blockIdx.x * 256 + tid;
    if (e >= j.esize) return;
    float v[NBASIS];
#pragma unroll
    for (int nb = 0; nb < NBASIS; nb++) v[nb] = j.src[nb * j.esize + e];
    for (int n = 0; n < NNEUR; n++) {
        float a = 0.f;
#pragma unroll
        for (int nb = 0; nb < NBASIS; nb++) a = fmaf(rs[n * NBASIS + nb], v[nb], a);
        j.dst[n * j.esize + e] = a;
    }
}

// ---------------- fused score + router ----------------
__global__ void scorerouter_kernel(const float* __restrict__ query, const float* __restrict__ nemb,
                                   int* __restrict__ topi, float* __restrict__ topw) {
    int t = blockIdx.x;
    int tid = threadIdx.x, warp = tid >> 5, lane = tid & 31;
    __shared__ float qrow[256];
    __shared__ float sc[NNEUR];
    __shared__ int   idxs[TOPK];
    __shared__ float wv[TOPK];
    qrow[tid] = query[t * 256 + tid];
    __syncthreads();
#pragma unroll
    for (int u = 0; u < 8; u++) {
        int n = warp * 8 + u;
        const float* nr = nemb + n * 256;
        float acc = 0.f;
#pragma unroll
        for (int i = 0; i < 8; i++) acc = fmaf(qrow[lane + 32 * i], nr[lane + 32 * i], acc);
#pragma unroll
        for (int o = 16; o; o >>= 1) acc += __shfl_down_sync(0xffffffffu, acc, o);
        if (!lane) sc[n] = acc;
    }
    __syncthreads();
    if (tid == 0) {
        float vals[TOPK];
        for (int kk = 0; kk < TOPK; kk++) {
            float best = -1e30f; int bi = 0;
            for (int n = 0; n < NNEUR; n++) if (sc[n] > best) { best = sc[n]; bi = n; }
            vals[kk] = best; idxs[kk] = bi; sc[bi] = -1e30f;
        }
        float mx = vals[0];
        float e[TOPK], s = 0.f;
        for (int kk = 0; kk < TOPK; kk++) { e[kk] = expf(vals[kk] - mx); s += e[kk]; }
        float invs = 1.f / s;
        for (int kk = 0; kk < TOPK; kk++) wv[kk] = e[kk] * invs;
    }
    __syncthreads();
    if (tid < TOPK) {
        topi[t * TOPK + tid] = idxs[tid];
        topw[t * TOPK + tid] = wv[tid];
    }
}

// ---------------- TT FFN stage A: 32 tokens/block (2 per warp), rank-split ----------------
struct SmemA {
    float N1[NNEUR * 128];
    float N2[NNEUR * 128];
    float xf[TPB_A][256];
    float a1[16][128];
    float a2[16][128];
    float tr[16][128];
};

__global__ __launch_bounds__(512) void stageA_kernel(
        const float* __restrict__ nrm2, const int* __restrict__ topi, const float* __restrict__ topw,
        const float* __restrict__ NA1, const float* __restrict__ NA2,
        float* __restrict__ hpart) {
    extern __shared__ float smemraw[];
    SmemA& S = *reinterpret_cast<SmemA*>(smemraw);
    int tid = threadIdx.x, tg = tid >> 5, lane = tid & 31;
    int t0 = blockIdx.x * TPB_A;
    int r0 = blockIdx.y * RPER_A;
    for (int u = tid; u < TPB_A * 64; u += 512)
        ((float4*)S.xf)[u] = ((const float4*)(nrm2 + t0 * 256))[u];
    __syncthreads();
    int nid[2][TOPK]; float nw[2][TOPK];
#pragma unroll
    for (int tok = 0; tok < 2; tok++) {
        int t = t0 + tg * 2 + tok;
#pragma unroll
        for (int kk = 0; kk < TOPK; kk++) { nid[tok][kk] = topi[t * TOPK + kk]; nw[tok][kk] = topw[t * TOPK + kk]; }
    }
    float hacc[2][2] = {{0.f, 0.f}, {0.f, 0.f}};
    int o = lane * 4;

    for (int ri = 0; ri < RPER_A; ri++) {
        int r = r0 + ri;
        __syncthreads();
#pragma unroll
        for (int it = 0; it < 4; it++) {
            int u = tid + it * 512;
            int n = u >> 5, rest = u & 31;
            int i = rest >> 1, kq = (rest & 1) * 4;
            *(float4*)&S.N1[n * 128 + i * 8 + kq] =
                *(const float4*)&NA1[n * 8192 + i * 512 + r * 8 + kq];
            *(float4*)&S.N2[n * 128 + rest * 4] =
                *(const float4*)&NA2[n * 8192 + r * 128 + rest * 4];
        }
        __syncthreads();
#pragma unroll
        for (int tok = 0; tok < 2; tok++) {
            int xrow = tg * 2 + tok;
            float m0 = 0, m1 = 0, m2 = 0, m3 = 0, p0 = 0, p1 = 0, p2 = 0, p3 = 0;
#pragma unroll
            for (int kk = 0; kk < TOPK; kk++) {
                float ww = nw[tok][kk];
                const float* s1 = &S.N1[nid[tok][kk] * 128 + o];
                const float* s2 = &S.N2[nid[tok][kk] * 128 + o];
                m0 = fmaf(ww, s1[0], m0); m1 = fmaf(ww, s1[1], m1);
                m2 = fmaf(ww, s1[2], m2); m3 = fmaf(ww, s1[3], m3);
                p0 = fmaf(ww, s2[0], p0); p1 = fmaf(ww, s2[1], p1);
                p2 = fmaf(ww, s2[2], p2); p3 = fmaf(ww, s2[3], p3);
            }
            S.a1[tg][o] = m0; S.a1[tg][o + 1] = m1; S.a1[tg][o + 2] = m2; S.a1[tg][o + 3] = m3;
            S.a2[tg][o] = p0; S.a2[tg][o + 1] = p1; S.a2[tg][o + 2] = p2; S.a2[tg][o + 3] = p3;
            __syncwarp();
#pragma unroll
            for (int qd = 0; qd < 4; qd++) {
                int idx = o + qd; int j = idx >> 3, kk = idx & 7;
                float s = 0.f;
#pragma unroll
                for (int i2 = 0; i2 < 16; i2++) s = fmaf(S.xf[xrow][i2 * 16 + j], S.a1[tg][i2 * 8 + kk], s);
                S.tr[tg][idx] = s;
            }
            __syncwarp();
#pragma unroll
            for (int qd = 0; qd < 2; qd++) {
                int idx = lane * 2 + qd; int kk = idx >> 3, l = idx & 7;
                float s = 0.f;
#pragma unroll
                for (int j = 0; j < 16; j++) s = fmaf(S.tr[tg][j * 8 + kk], S.a2[tg][j * 8 + l], s);
                hacc[tok][qd] += s;
            }
            __syncwarp();
        }
    }
#pragma unroll
    for (int tok = 0; tok < 2; tok++) {
        int t = t0 + tg * 2 + tok;
        hpart[(blockIdx.y * T_TOK + t) * 64 + lane * 2]     = hacc[tok][0];
        hpart[(blockIdx.y * T_TOK + t) * 64 + lane * 2 + 1] = hacc[tok][1];
    }
}

// ---------------- TT FFN stage B: 32 tokens/block (2 per warp), rank-split, fused h-reduce ----------------
struct SmemB {
    float N1[NNEUR * 256];
    float N2[NNEUR * 256];
    float tr[16][256];
    float hf[TPB_B][64];
};

__global__ __launch_bounds__(512) void stageB_kernel(
        const float* __restrict__ hpart, const int* __restrict__ topi, const float* __restrict__ topw,
        const float* __restrict__ NB1, const float* __restrict__ NB2,
        float* __restrict__ ffnpart) {
    extern __shared__ float smemraw[];
    SmemB& S = *reinterpret_cast<SmemB*>(smemraw);
    int tid = threadIdx.x, tg = tid >> 5, lane = tid & 31;
    int t0 = blockIdx.x * TPB_B;
    int r0 = blockIdx.y * RPER_B;
    for (int u = tid; u < TPB_B * 64; u += 512) {
        float s = 0.f;
#pragma unroll
        for (int g = 0; g < RG_A; g++) s += hpart[g * (T_TOK * 64) + t0 * 64 + u];
        S.hf[0][u] = s;
    }
    __syncthreads();
    int nid[2][TOPK]; float nw[2][TOPK];
#pragma unroll
    for (int tok = 0; tok < 2; tok++) {
        int t = t0 + tg * 2 + tok;
#pragma unroll
        for (int kk = 0; kk < TOPK; kk++) { nid[tok][kk] = topi[t * TOPK + kk]; nw[tok][kk] = topw[t * TOPK + kk]; }
    }
    float oreg[2][32];
#pragma unroll
    for (int tok = 0; tok < 2; tok++)
#pragma unroll
        for (int i = 0; i < 32; i++) oreg[tok][i] = 0.f;

    for (int ri = 0; ri < RPER_B; ri++) {
        int r = r0 + ri;
        __syncthreads();
#pragma unroll
        for (int it = 0; it < 8; it++) {
            int u = tid + it * 512;
            int n = u >> 6, rest = u & 63;
            int i = rest >> 3, kq = (rest & 7) * 4;
            *(float4*)&S.N1[n * 256 + i * 32 + kq] =
                *(const float4*)&NB1[n * 16384 + i * 2048 + r * 32 + kq];
            *(float4*)&S.N2[n * 256 + rest * 4] =
                *(const float4*)&NB2[n * 16384 + r * 256 + rest * 4];
        }
        __syncthreads();
#pragma unroll
        for (int tok = 0; tok < 2; tok++) {
            int xrow = tg * 2 + tok;
            float b1r[8], b2r[8];
#pragma unroll
            for (int i = 0; i < 8; i++) {
                float s1 = 0.f, s2 = 0.f;
#pragma unroll
                for (int kk = 0; kk < TOPK; kk++) {
                    s1 = fmaf(nw[tok][kk], S.N1[nid[tok][kk] * 256 + i * 32 + lane], s1);
                    s2 = fmaf(nw[tok][kk], S.N2[nid[tok][kk] * 256 + i * 32 + lane], s2);
                }
                b1r[i] = s1; b2r[i] = s2;
            }
#pragma unroll
            for (int j = 0; j < 8; j++) {
                float s = 0.f;
#pragma unroll
                for (int i2 = 0; i2 < 8; i2++) s = fmaf(S.hf[xrow][i2 * 8 + j], b1r[i2], s);
                S.tr[tg][j * 32 + lane] = s;
            }
            __syncwarp();
#pragma unroll
            for (int kk = 0; kk < 32; kk++) {
                float s = 0.f;
#pragma unroll
                for (int j = 0; j < 8; j++) s = fmaf(S.tr[tg][j * 32 + kk], b2r[j], s);
                oreg[tok][kk] += s;
            }
            __syncwarp();
        }
    }
#pragma unroll
    for (int tok = 0; tok < 2; tok++) {
        int t = t0 + tg * 2 + tok;
        float* dst = ffnpart + (blockIdx.y * T_TOK + t) * (size_t)DFF;
#pragma unroll
        for (int kk = 0; kk < 32; kk++) dst[kk * 32 + lane] = oreg[tok][kk];
    }
}

__global__ void gelu_reduce_kernel(const float* __restrict__ ffnpart, float* __restrict__ ffn) {
    int idx = blockIdx.x * 256 + threadIdx.x;
    float s = 0.f;
#pragma unroll
    for (int g = 0; g < RG_B; g++) s += ffnpart[g * (size_t)(T_TOK * DFF) + idx];
    ffn[idx] = 0.5f * s * (1.f + erff(s * 0.70710678118654752f));
}

// ---------------- host orchestration ----------------
extern "C" void kernel_launch(void* const* d_in, const int* in_sizes, int n_in,
                              void* d_out, int out_size) {
    const int*   ids    = (const int*)d_in[0];
    const float* te     = (const float*)d_in[1];
    const float* pe     = (const float*)d_in[2];
    const float* qW     = (const float*)d_in[3];
    const float* qb     = (const float*)d_in[4];
    const float* kW     = (const float*)d_in[5];
    const float* kb     = (const float*)d_in[6];
    const float* vW     = (const float*)d_in[7];
    const float* vb     = (const float*)d_in[8];
    const float* sW     = (const float*)d_in[9];
    const float* sb     = (const float*)d_in[10];
    const float* recipes= (const float*)d_in[11];
    const float* wdW    = (const float*)d_in[12];
    const float* wdb    = (const float*)d_in[13];
    const float* n1g    = (const float*)d_in[14];
    const float* n1b    = (const float*)d_in[15];
    const float* n2g    = (const float*)d_in[16];
    const float* n2b    = (const float*)d_in[17];
    const float* basis  = (const float*)d_in[18];
    const float* A1     = (const float*)d_in[19];
    const float* A2     = (const float*)d_in[20];
    const float* B1     = (const float*)d_in[21];
    const float* B2     = (const float*)d_in[22];
    const float* fng    = (const float*)d_in[23];
    const float* fnb    = (const float*)d_in[24];
    float* out = (float*)d_out;

    float *x, *nrm1, *q, *k, *v, *ctx, *query, *nrm2, *ffn, *Rsoft, *nemb, *hpart, *ffnpart, *wdpart;
    float *NA1, *NA2, *NB1, *NB2, *topw;
    int* topi;
    cudaGetSymbolAddress((void**)&x, g_x);
    cudaGetSymbolAddress((void**)&nrm1, g_nrm1);
    cudaGetSymbolAddress((void**)&q, g_q);
    cudaGetSymbolAddress((void**)&k, g_k);
    cudaGetSymbolAddress((void**)&v, g_v);
    cudaGetSymbolAddress((void**)&ctx, g_ctx);
    cudaGetSymbolAddress((void**)&query, g_query);
    cudaGetSymbolAddress((void**)&nrm2, g_nrm2);
    cudaGetSymbolAddress((void**)&ffn, g_ffn);
    cudaGetSymbolAddress((void**)&Rsoft, g_Rsoft);
    cudaGetSymbolAddress((void**)&nemb, g_nemb);
    cudaGetSymbolAddress((void**)&hpart, g_hpart);
    cudaGetSymbolAddress((void**)&ffnpart, g_ffnpart);
    cudaGetSymbolAddress((void**)&wdpart, g_wdpart);
    cudaGetSymbolAddress((void**)&NA1, g_NA1);
    cudaGetSymbolAddress((void**)&NA2, g_NA2);
    cudaGetSymbolAddress((void**)&NB1, g_NB1);
    cudaGetSymbolAddress((void**)&NB2, g_NB2);
    cudaGetSymbolAddress((void**)&topi, g_topi);
    cudaGetSymbolAddress((void**)&topw, g_topw);

    cudaFuncSetAttribute(stageA_kernel, cudaFuncAttributeMaxDynamicSharedMemorySize, (int)sizeof(SmemA));
    cudaFuncSetAttribute(stageB_kernel, cudaFuncAttributeMaxDynamicSharedMemorySize, (int)sizeof(SmemB));
    cudaFuncSetAttribute(fattn_kernel, cudaFuncAttributeMaxDynamicSharedMemorySize, FA_SMEM);

    embed_kernel<<<T_TOK, 256>>>(ids, te, pe, x);

    dim3 g44(4, 16);
    for (int l = 0; l < NLAYER; l++) {
        ln_kernel<<<T_TOK, 256>>>(x, n1g + l * 256, n1b + l * 256, nrm1);
        W4 gb;
        gb.W[0] = qW + l * 65536;  gb.bias[0] = qb + l * 256; gb.out[0] = q;
        gb.W[1] = kW + l * 65536;  gb.bias[1] = kb + l * 256; gb.out[1] = k;
        gb.W[2] = vW + l * 65536;  gb.bias[2] = vb + l * 256; gb.out[2] = v;
        gb.W[3] = sW + l * 131072; gb.bias[3] = nullptr;      gb.out[3] = query;
        tc_gemmb<<<dim3(4, 16, 4), 256>>>(nrm1, gb, 1024, 256, 256);
        fattn_kernel<<<dim3(16, 8), 128, FA_SMEM>>>(q, k, v, ctx);
        tc_gemm<<<g44, 256>>>(ctx, sW + l * 131072 + 65536, sb + l * 256, query, 1024, 256, 256, 1.f);
        rsoft_kernel<<<1, 256>>>(recipes + l * 2048, basis, Rsoft, nemb);
        NCJ j0{A1, NA1, 8192}, j1{A2, NA2, 8192}, j2{B1, NB1, 16384}, j3{B2, NB2, 16384};
        ncore4_kernel<<<dim3(64, 4), 256>>>(Rsoft, j0, j1, j2, j3);
        scorerouter_kernel<<<T_TOK, 256>>>(query, nemb, topi, topw);
        ln_kernel<<<T_TOK, 256>>>(x, n2g + l * 256, n2b + l * 256, nrm2);
        stageA_kernel<<<dim3(T_TOK / TPB_A, RG_A), 512, sizeof(SmemA)>>>(nrm2, topi, topw, NA1, NA2, hpart);
        stageB_kernel<<<dim3(T_TOK / TPB_B, RG_B), 512, sizeof(SmemB)>>>(hpart, topi, topw, NB1, NB2, ffnpart);
        gelu_reduce_kernel<<<T_TOK * DFF / 256, 256>>>(ffnpart, ffn);
        tc_gemm_sk<<<dim3(4, 16, 2), 256>>>(ffn, wdW + l * 262144, wdpart, 256, 1024, 512);
        wdadd_kernel<<<T_TOK, 256>>>(wdpart, wdb + l * 256, x);
    }
    ln_kernel<<<T_TOK, 256>>>(x, fng, fnb, nrm1);
    hg_kernel<<<dim3(VOCAB / 64, T_TOK / 128), 256>>>(nrm1, te, out, 1024, VOCAB, 256);
}